// round 1
// baseline (speedup 1.0000x reference)
#include <cuda_runtime.h>
#include <cstdint>

#define N_NODES 100000
#define VF      128
#define FILT    64
#define NH      3          // heads
#define KNBR    10
#define NCOLS   384        // [Zc (3*64) | Zn_src (3*64)]
#define OUTC    192

// ---------------- scratch (static device globals; no cudaMalloc allowed) ---
__device__ float g_Z[2][(size_t)N_NODES * NCOLS];   // per-branch Z: rows node-major
__device__ float g_B[2][VF * NCOLS];                // prepacked weights [k][c]
__device__ float g_s1[2][N_NODES * NH];
__device__ float g_s2[2][N_NODES * NH];

// ---------------- prepack weights: B[k][c] --------------------------------
// c < 192: Wvc[h][k][o]  (h=c/64, o=c%64) ; c>=192: Wvn[h][k][o]
__global__ void prepack_kernel(const float* __restrict__ Wvc,
                               const float* __restrict__ Wvn, int branch) {
    int i = blockIdx.x * blockDim.x + threadIdx.x;
    if (i >= VF * NCOLS) return;
    int k = i / NCOLS;
    int c = i % NCOLS;
    float v;
    if (c < OUTC) {
        int h = c / FILT, o = c % FILT;
        v = Wvc[((size_t)h * VF + k) * FILT + o];
    } else {
        int c2 = c - OUTC;
        int h = c2 / FILT, o = c2 % FILT;
        v = Wvn[((size_t)h * VF + k) * FILT + o];
    }
    g_B[branch][i] = v;
}

// ---------------- SGEMM: Z[b] = (mask*verts)[N x 128] @ B[b][128 x 384] ----
#define BM 128
#define BN 128
#define BK 8
#define TM 8
#define TN 8

__global__ __launch_bounds__(256, 2)
void gemm_kernel(const float* __restrict__ A, const int* __restrict__ is_int,
                 int branch) {
    __shared__ float As[BK][BM];
    __shared__ float Bs[BK][BN];

    const int tid = threadIdx.x;
    const int bm = blockIdx.x * BM;
    const int bn = blockIdx.y * BN;
    const float* __restrict__ Bg = g_B[branch];
    float* __restrict__ C = g_Z[branch];

    // A-tile load mapping: thread -> (row ra, 4 cols at ka)
    const int ra = tid >> 1;            // 0..127
    const int ka = (tid & 1) << 2;      // 0 or 4
    const int grow = bm + ra;
    float m = 0.f;
    if (grow < N_NODES) {
        int ii = is_int[grow];
        m = ((branch == 0) == (ii == 1)) ? 1.f : 0.f;
    }
    const float* __restrict__ Aptr =
        A + (size_t)(grow < N_NODES ? grow : 0) * VF + ka;

    // B-tile load mapping
    const int rb = tid >> 5;            // 0..7
    const int cb = (tid & 31) << 2;     // 0..124

    const int tm = (tid >> 4) << 3;
    const int tn = (tid & 15) << 3;

    float acc[TM][TN];
#pragma unroll
    for (int i = 0; i < TM; i++)
#pragma unroll
        for (int j = 0; j < TN; j++) acc[i][j] = 0.f;

#pragma unroll 1
    for (int k0 = 0; k0 < VF; k0 += BK) {
        float4 av = *(const float4*)(Aptr + k0);
        float4 bv4 = *(const float4*)(Bg + (size_t)(k0 + rb) * NCOLS + bn + cb);
        As[ka + 0][ra] = av.x * m;
        As[ka + 1][ra] = av.y * m;
        As[ka + 2][ra] = av.z * m;
        As[ka + 3][ra] = av.w * m;
        *(float4*)&Bs[rb][cb] = bv4;
        __syncthreads();
#pragma unroll
        for (int kk = 0; kk < BK; kk++) {
            float af[TM], bf[TN];
            *(float4*)&af[0] = *(const float4*)&As[kk][tm];
            *(float4*)&af[4] = *(const float4*)&As[kk][tm + 4];
            *(float4*)&bf[0] = *(const float4*)&Bs[kk][tn];
            *(float4*)&bf[4] = *(const float4*)&Bs[kk][tn + 4];
#pragma unroll
            for (int i = 0; i < TM; i++)
#pragma unroll
                for (int j = 0; j < TN; j++)
                    acc[i][j] += af[i] * bf[j];
        }
        __syncthreads();
    }

#pragma unroll
    for (int i = 0; i < TM; i++) {
        int r = bm + tm + i;
        if (r < N_NODES) {
            float* Crow = C + (size_t)r * NCOLS + bn + tn;
            float4 v0 = make_float4(acc[i][0], acc[i][1], acc[i][2], acc[i][3]);
            float4 v1 = make_float4(acc[i][4], acc[i][5], acc[i][6], acc[i][7]);
            *(float4*)&Crow[0] = v0;
            *(float4*)&Crow[4] = v1;
        }
    }
}

// ---------------- s1/s2: per-node attention scalars -----------------------
// a: (H, 2*FILT) flat; a1[h][o]=a[h*128+o], a2[h][o]=a[h*128+64+o]
__global__ __launch_bounds__(256)
void s_kernel(const float* __restrict__ a, int branch) {
    int gw = (blockIdx.x * blockDim.x + threadIdx.x) >> 5;
    int lane = threadIdx.x & 31;
    if (gw >= N_NODES) return;
    const float* __restrict__ row = g_Z[branch] + (size_t)gw * NCOLS;
#pragma unroll
    for (int h = 0; h < NH; h++) {
        float v1 = row[OUTC + h * FILT + lane]      * a[h * 128 + lane]
                 + row[OUTC + h * FILT + 32 + lane] * a[h * 128 + 32 + lane];
        float v2 = row[h * FILT + lane]      * a[h * 128 + 64 + lane]
                 + row[h * FILT + 32 + lane] * a[h * 128 + 96 + lane];
#pragma unroll
        for (int o = 16; o; o >>= 1) {
            v1 += __shfl_xor_sync(0xffffffffu, v1, o);
            v2 += __shfl_xor_sync(0xffffffffu, v2, o);
        }
        if (lane == 0) {
            g_s1[branch][gw * NH + h] = v1;
            g_s2[branch][gw * NH + h] = v2;
        }
    }
}

// ---------------- attention + aggregate + epilogue ------------------------
__global__ __launch_bounds__(256)
void attn_kernel(const int* __restrict__ idx, const float* __restrict__ edges,
                 const float* __restrict__ bv, int branch,
                 float* __restrict__ out) {
    int gw = (blockIdx.x * blockDim.x + threadIdx.x) >> 5;
    int lane = threadIdx.x & 31;
    if (gw >= N_NODES) return;
    const int n = gw;

    const float* __restrict__ Zbase = g_Z[branch];
    const float* __restrict__ s1 = g_s1[branch];
    const float* __restrict__ s2 = g_s2[branch];

    int myidx = -1;
    float myedge = 0.f;
    if (lane < KNBR) {
        myidx = idx[(size_t)n * KNBR + lane];
        myedge = edges[(size_t)n * KNBR + lane];
    }
    float part = (lane < KNBR && myidx >= 0) ? 1.f : 0.f;

    float cnt = part;
#pragma unroll
    for (int o = 16; o; o >>= 1) cnt += __shfl_xor_sync(0xffffffffu, cnt, o);
    const float invnorm = 1.f / fmaxf(cnt, 1.f);

#pragma unroll
    for (int h = 0; h < NH; h++) {
        float s2h = s2[(size_t)n * NH + h];
        float e = 0.f;
        if (part != 0.f) e = (s1[(size_t)myidx * NH + h] + s2h) * myedge;

        float emax = (lane < KNBR) ? e : -1e30f;
#pragma unroll
        for (int o = 16; o; o >>= 1)
            emax = fmaxf(emax, __shfl_xor_sync(0xffffffffu, emax, o));
        float p = (lane < KNBR) ? expf(e - emax) : 0.f;
        float psum = p;
#pragma unroll
        for (int o = 16; o; o >>= 1) psum += __shfl_xor_sync(0xffffffffu, psum, o);
        float w = (p / psum) * part * invnorm;

        float2 acc = make_float2(0.f, 0.f);
#pragma unroll
        for (int k = 0; k < KNBR; k++) {
            float wk = __shfl_sync(0xffffffffu, w, k);
            int ik = __shfl_sync(0xffffffffu, myidx, k);
            if (ik >= 0) {
                const float2 g = *(const float2*)(Zbase + (size_t)ik * NCOLS +
                                                  OUTC + h * FILT + lane * 2);
                acc.x += wk * g.x;
                acc.y += wk * g.y;
            }
        }

        const float2 zc = *(const float2*)(Zbase + (size_t)n * NCOLS +
                                           h * FILT + lane * 2);
        float b0 = bv[h * FILT + lane * 2];
        float b1 = bv[h * FILT + lane * 2 + 1];
        float2 o2;
        o2.x = fmaxf(zc.x + acc.x + b0, 0.f);
        o2.y = fmaxf(zc.y + acc.y + b1, 0.f);
        *(float2*)(out + (size_t)n * OUTC + h * FILT + lane * 2) = o2;
    }
}

// ---------------- launch ---------------------------------------------------
extern "C" void kernel_launch(void* const* d_in, const int* in_sizes, int n_in,
                              void* d_out, int out_size) {
    const float* vertices_int = (const float*)d_in[0];
    const float* vertices_nh  = (const float*)d_in[1];
    const int*   nh_indices   = (const int*)d_in[2];
    const int*   int_indices  = (const int*)d_in[3];
    const float* nh_edges     = (const float*)d_in[4];
    const float* int_edges    = (const float*)d_in[5];
    const int*   is_int       = (const int*)d_in[6];
    const float* Wvc_int      = (const float*)d_in[7];
    const float* Wvc_nh       = (const float*)d_in[8];
    const float* Wvn_int      = (const float*)d_in[9];
    const float* Wvn_nh       = (const float*)d_in[10];
    const float* bv_int       = (const float*)d_in[11];
    const float* bv_nh        = (const float*)d_in[12];
    const float* a_int        = (const float*)d_in[13];
    const float* a_nh         = (const float*)d_in[14];
    float* out = (float*)d_out;

    const int PREP_BLOCKS = (VF * NCOLS + 255) / 256;
    prepack_kernel<<<PREP_BLOCKS, 256>>>(Wvc_int, Wvn_int, 0);
    prepack_kernel<<<PREP_BLOCKS, 256>>>(Wvc_nh,  Wvn_nh,  1);

    dim3 gg((N_NODES + BM - 1) / BM, NCOLS / BN);
    const int WARP_BLOCKS = (N_NODES + 7) / 8;   // 8 warps per 256-thread block

    // branch 0 = int
    gemm_kernel<<<gg, 256>>>(vertices_int, is_int, 0);
    s_kernel<<<WARP_BLOCKS, 256>>>(a_int, 0);
    attn_kernel<<<WARP_BLOCKS, 256>>>(int_indices, int_edges, bv_int, 0, out);

    // branch 1 = nh
    gemm_kernel<<<gg, 256>>>(vertices_nh, is_int, 1);
    s_kernel<<<WARP_BLOCKS, 256>>>(a_nh, 1);
    attn_kernel<<<WARP_BLOCKS, 256>>>(nh_indices, nh_edges, bv_nh, 1,
                                      out + (size_t)N_NODES * OUTC);
}

// round 2
// speedup vs baseline: 1.6456x; 1.6456x over previous
#include <cuda_runtime.h>
#include <cstdint>

#define N_NODES 100000
#define VF      128
#define FILT    64
#define NH      3
#define KNBR    10
#define ZC      192        // cols per region (Zc or Zn)
#define NCOLS   384        // GEMM output cols: [Zc 192 | Zn 192]
#define OUTC    192

// ---------------- scratch (static device globals) --------------------------
__device__ float g_Zc[2][(size_t)N_NODES * ZC];
__device__ float g_Zn[2][(size_t)N_NODES * ZC];
__device__ float g_B [2][VF * NCOLS];          // prepacked weights [k][c]
__device__ float g_w1[2][NH * VF];             // Wvn @ a1  (per head)
__device__ float g_w2[2][NH * VF];             // Wvc @ a2
__device__ float g_s1[2][(size_t)N_NODES * NH];
__device__ float g_s2[2][(size_t)N_NODES * NH];
__device__ int   g_perm[2][N_NODES];
__device__ int   g_cnt[2];

// ---------------- prepack weights: B[k][c] ---------------------------------
__global__ void prepack_kernel(const float* __restrict__ Wvc,
                               const float* __restrict__ Wvn, int branch) {
    int i = blockIdx.x * blockDim.x + threadIdx.x;
    if (i >= VF * NCOLS) return;
    int k = i / NCOLS;
    int c = i % NCOLS;
    float v;
    if (c < ZC) {
        int h = c / FILT, o = c % FILT;
        v = Wvc[((size_t)h * VF + k) * FILT + o];
    } else {
        int c2 = c - ZC;
        int h = c2 / FILT, o = c2 % FILT;
        v = Wvn[((size_t)h * VF + k) * FILT + o];
    }
    g_B[branch][i] = v;
}

// ---------------- fold attention vectors: w1 = Wvn@a1, w2 = Wvc@a2 ---------
__global__ void wvec_kernel(const float* __restrict__ Wvc,
                            const float* __restrict__ Wvn,
                            const float* __restrict__ a, int branch) {
    int gw = (blockIdx.x * blockDim.x + threadIdx.x) >> 5;   // (h,k) pair id
    int lane = threadIdx.x & 31;
    if (gw >= NH * VF) return;
    int h = gw / VF, k = gw % VF;
    const float* wn = Wvn + ((size_t)h * VF + k) * FILT;
    const float* wc = Wvc + ((size_t)h * VF + k) * FILT;
    float v1 = wn[lane] * a[h * 128 + lane] + wn[lane + 32] * a[h * 128 + lane + 32];
    float v2 = wc[lane] * a[h * 128 + 64 + lane] + wc[lane + 32] * a[h * 128 + 96 + lane];
#pragma unroll
    for (int o = 16; o; o >>= 1) {
        v1 += __shfl_xor_sync(0xffffffffu, v1, o);
        v2 += __shfl_xor_sync(0xffffffffu, v2, o);
    }
    if (lane == 0) {
        g_w1[branch][h * VF + k] = v1;
        g_w2[branch][h * VF + k] = v2;
    }
}

// ---------------- compaction ------------------------------------------------
__global__ void reset_kernel() {
    if (threadIdx.x == 0) { g_cnt[0] = 0; g_cnt[1] = 0; }
}

__global__ void compact_kernel(const int* __restrict__ is_int) {
    int n = blockIdx.x * blockDim.x + threadIdx.x;
    if (n >= N_NODES) return;
    int b = (is_int[n] == 1) ? 0 : 1;
    int pos = atomicAdd(&g_cnt[b], 1);
    g_perm[b][pos] = n;
}

// ---------------- s1/s2 direct from vertices --------------------------------
// One warp per node. Only the node's active branch gets real values; the
// other branch gets zeros (needed: attn reads s1[idx]/s2[n] unconditionally).
__global__ __launch_bounds__(256)
void s_kernel(const float* __restrict__ v_int, const float* __restrict__ v_nh,
              const int* __restrict__ is_int) {
    int n = (blockIdx.x * blockDim.x + threadIdx.x) >> 5;
    int lane = threadIdx.x & 31;
    if (n >= N_NODES) return;
    int b = (is_int[n] == 1) ? 0 : 1;
    const float* v = (b == 0 ? v_int : v_nh) + (size_t)n * VF;
    float4 x = *(const float4*)(v + lane * 4);
#pragma unroll
    for (int h = 0; h < NH; h++) {
        float4 w1 = *(const float4*)(g_w1[b] + h * VF + lane * 4);
        float4 w2 = *(const float4*)(g_w2[b] + h * VF + lane * 4);
        float v1 = x.x * w1.x + x.y * w1.y + x.z * w1.z + x.w * w1.w;
        float v2 = x.x * w2.x + x.y * w2.y + x.z * w2.z + x.w * w2.w;
#pragma unroll
        for (int o = 16; o; o >>= 1) {
            v1 += __shfl_xor_sync(0xffffffffu, v1, o);
            v2 += __shfl_xor_sync(0xffffffffu, v2, o);
        }
        if (lane == 0) {
            g_s1[b][(size_t)n * NH + h] = v1;
            g_s2[b][(size_t)n * NH + h] = v2;
            g_s1[1 - b][(size_t)n * NH + h] = 0.f;
            g_s2[1 - b][(size_t)n * NH + h] = 0.f;
        }
    }
}

// ---------------- SGEMM on compacted rows (fma.rn.f32x2 inner loop) --------
#define BM 128
#define BN 128
#define BK 8
#define TM 8
#define TN 8

__global__ __launch_bounds__(256, 2)
void gemm_kernel(const float* __restrict__ A, int branch) {
    __shared__ float As[BK][BM];
    __shared__ float Bs[BK][BN];

    const int cnt = g_cnt[branch];
    const int bm = blockIdx.x * BM;
    if (bm >= cnt) return;
    const int bn = blockIdx.y * BN;
    const int tid = threadIdx.x;

    // A-tile load mapping
    const int ra = tid >> 1;
    const int ka = (tid & 1) << 2;
    const int arow = bm + ra;
    const int anode = g_perm[branch][arow < cnt ? arow : cnt - 1];
    const float* __restrict__ Aptr = A + (size_t)anode * VF + ka;

    // B-tile load mapping
    const int rb = tid >> 5;
    const int cb = (tid & 31) << 2;
    const float* __restrict__ Bg = g_B[branch] + (size_t)rb * NCOLS + bn + cb;

    const int tm = (tid >> 4) << 3;
    const int tn = (tid & 15) << 3;

    unsigned long long acc[TM][4];
#pragma unroll
    for (int i = 0; i < TM; i++)
#pragma unroll
        for (int j = 0; j < 4; j++) acc[i][j] = 0ull;

#pragma unroll 1
    for (int k0 = 0; k0 < VF; k0 += BK) {
        float4 av = *(const float4*)(Aptr + k0);
        float4 bv4 = *(const float4*)(Bg + (size_t)k0 * NCOLS);
        As[ka + 0][ra] = av.x;
        As[ka + 1][ra] = av.y;
        As[ka + 2][ra] = av.z;
        As[ka + 3][ra] = av.w;
        *(float4*)&Bs[rb][cb] = bv4;
        __syncthreads();
#pragma unroll
        for (int kk = 0; kk < BK; kk++) {
            float af[TM];
            *(float4*)&af[0] = *(const float4*)&As[kk][tm];
            *(float4*)&af[4] = *(const float4*)&As[kk][tm + 4];
            ulonglong2 b01 = *(const ulonglong2*)&Bs[kk][tn];
            ulonglong2 b23 = *(const ulonglong2*)&Bs[kk][tn + 4];
            unsigned long long bp0 = b01.x, bp1 = b01.y, bp2 = b23.x, bp3 = b23.y;
#pragma unroll
            for (int i = 0; i < TM; i++) {
                unsigned long long aa;
                asm("mov.b64 %0, {%1, %1};" : "=l"(aa) : "f"(af[i]));
                asm("fma.rn.f32x2 %0, %1, %2, %0;" : "+l"(acc[i][0]) : "l"(aa), "l"(bp0));
                asm("fma.rn.f32x2 %0, %1, %2, %0;" : "+l"(acc[i][1]) : "l"(aa), "l"(bp1));
                asm("fma.rn.f32x2 %0, %1, %2, %0;" : "+l"(acc[i][2]) : "l"(aa), "l"(bp2));
                asm("fma.rn.f32x2 %0, %1, %2, %0;" : "+l"(acc[i][3]) : "l"(aa), "l"(bp3));
            }
        }
        __syncthreads();
    }

    // epilogue: scatter rows to their node slots; split Zc / Zn regions
    const int col0 = bn + tn;                    // multiple of 8
    const bool isZc = (col0 < ZC);
    float* __restrict__ base = isZc ? g_Zc[branch] : g_Zn[branch];
    const int coff = isZc ? col0 : col0 - ZC;
#pragma unroll
    for (int i = 0; i < TM; i++) {
        int r = bm + tm + i;
        if (r < cnt) {
            int nd = g_perm[branch][r];
            float* dst = base + (size_t)nd * ZC + coff;
            float2 p0 = *(float2*)&acc[i][0];
            float2 p1 = *(float2*)&acc[i][1];
            float2 p2 = *(float2*)&acc[i][2];
            float2 p3 = *(float2*)&acc[i][3];
            *(float4*)&dst[0] = make_float4(p0.x, p0.y, p1.x, p1.y);
            *(float4*)&dst[4] = make_float4(p2.x, p2.y, p3.x, p3.y);
        }
    }
}

// ---------------- attention + aggregate + epilogue --------------------------
__global__ __launch_bounds__(256)
void attn_kernel(const int* __restrict__ idx, const float* __restrict__ edges,
                 const float* __restrict__ bv, const int* __restrict__ is_int,
                 int branch, float* __restrict__ out) {
    int n = (blockIdx.x * blockDim.x + threadIdx.x) >> 5;
    int lane = threadIdx.x & 31;
    if (n >= N_NODES) return;

    const float* __restrict__ Zn = g_Zn[branch];
    const float* __restrict__ s1 = g_s1[branch];
    const float* __restrict__ s2 = g_s2[branch];

    const bool nact = (branch == 0) == (is_int[n] == 1);

    int myidx = -1;
    float myedge = 0.f;
    if (lane < KNBR) {
        myidx = idx[(size_t)n * KNBR + lane];
        myedge = edges[(size_t)n * KNBR + lane];
    }
    const bool has = (lane < KNBR) && (myidx >= 0);
    float part = has ? 1.f : 0.f;
    int gact = 0;   // neighbor is active in this branch -> its Zn row is nonzero
    if (has) gact = ((branch == 0) == (is_int[myidx] == 1)) ? 1 : 0;

    float cntp = part;
#pragma unroll
    for (int o = 16; o; o >>= 1) cntp += __shfl_xor_sync(0xffffffffu, cntp, o);
    const float invnorm = 1.f / fmaxf(cntp, 1.f);

#pragma unroll
    for (int h = 0; h < NH; h++) {
        float s2h = s2[(size_t)n * NH + h];
        float e = 0.f;
        if (has) e = (s1[(size_t)myidx * NH + h] + s2h) * myedge;

        float emax = (lane < KNBR) ? e : -1e30f;
#pragma unroll
        for (int o = 16; o; o >>= 1)
            emax = fmaxf(emax, __shfl_xor_sync(0xffffffffu, emax, o));
        float p = (lane < KNBR) ? expf(e - emax) : 0.f;
        float psum = p;
#pragma unroll
        for (int o = 16; o; o >>= 1) psum += __shfl_xor_sync(0xffffffffu, psum, o);
        float w = (p / psum) * part * invnorm;

        float2 acc = make_float2(0.f, 0.f);
#pragma unroll
        for (int k = 0; k < KNBR; k++) {
            float wk = __shfl_sync(0xffffffffu, w, k);
            int ik = __shfl_sync(0xffffffffu, myidx, k);
            int gk = __shfl_sync(0xffffffffu, gact, k);
            if (gk) {
                const float2 g = *(const float2*)(Zn + (size_t)ik * ZC +
                                                  h * FILT + lane * 2);
                acc.x += wk * g.x;
                acc.y += wk * g.y;
            }
        }

        float2 zc = make_float2(0.f, 0.f);
        if (nact)
            zc = *(const float2*)(g_Zc[branch] + (size_t)n * ZC + h * FILT + lane * 2);
        float b0 = bv[h * FILT + lane * 2];
        float b1 = bv[h * FILT + lane * 2 + 1];
        float2 o2;
        o2.x = fmaxf(zc.x + acc.x + b0, 0.f);
        o2.y = fmaxf(zc.y + acc.y + b1, 0.f);
        *(float2*)(out + (size_t)n * OUTC + h * FILT + lane * 2) = o2;
    }
}

// ---------------- launch ----------------------------------------------------
extern "C" void kernel_launch(void* const* d_in, const int* in_sizes, int n_in,
                              void* d_out, int out_size) {
    const float* vertices_int = (const float*)d_in[0];
    const float* vertices_nh  = (const float*)d_in[1];
    const int*   nh_indices   = (const int*)d_in[2];
    const int*   int_indices  = (const int*)d_in[3];
    const float* nh_edges     = (const float*)d_in[4];
    const float* int_edges    = (const float*)d_in[5];
    const int*   is_int       = (const int*)d_in[6];
    const float* Wvc_int      = (const float*)d_in[7];
    const float* Wvc_nh       = (const float*)d_in[8];
    const float* Wvn_int      = (const float*)d_in[9];
    const float* Wvn_nh       = (const float*)d_in[10];
    const float* bv_int       = (const float*)d_in[11];
    const float* bv_nh        = (const float*)d_in[12];
    const float* a_int        = (const float*)d_in[13];
    const float* a_nh         = (const float*)d_in[14];
    float* out = (float*)d_out;

    const int PREP_BLOCKS = (VF * NCOLS + 255) / 256;
    prepack_kernel<<<PREP_BLOCKS, 256>>>(Wvc_int, Wvn_int, 0);
    prepack_kernel<<<PREP_BLOCKS, 256>>>(Wvc_nh,  Wvn_nh,  1);
    const int WV_BLOCKS = (NH * VF * 32 + 255) / 256;
    wvec_kernel<<<WV_BLOCKS, 256>>>(Wvc_int, Wvn_int, a_int, 0);
    wvec_kernel<<<WV_BLOCKS, 256>>>(Wvc_nh,  Wvn_nh,  a_nh,  1);

    reset_kernel<<<1, 32>>>();
    compact_kernel<<<(N_NODES + 255) / 256, 256>>>(is_int);

    const int WARP_BLOCKS = (N_NODES + 7) / 8;
    s_kernel<<<WARP_BLOCKS, 256>>>(vertices_int, vertices_nh, is_int);

    dim3 gg((N_NODES + BM - 1) / BM, NCOLS / BN);
    gemm_kernel<<<gg, 256>>>(vertices_int, 0);
    gemm_kernel<<<gg, 256>>>(vertices_nh, 1);

    attn_kernel<<<WARP_BLOCKS, 256>>>(int_indices, int_edges, bv_int, is_int,
                                      0, out);
    attn_kernel<<<WARP_BLOCKS, 256>>>(nh_indices, nh_edges, bv_nh, is_int,
                                      1, out + (size_t)N_NODES * OUTC);
}

// round 4
// speedup vs baseline: 1.9631x; 1.1930x over previous
#include <cuda_runtime.h>
#include <cstdint>

#define N_NODES 100000
#define VF      128
#define FILT    64
#define NH      3
#define KNBR    10
#define ZC      192
#define NCOLS   384
#define OUTC    192

// ---------------- scratch (static device globals) --------------------------
__device__ float g_Zc[2][(size_t)N_NODES * ZC];   // compacted rows
__device__ float g_Zn[2][(size_t)N_NODES * ZC];   // compacted rows
__device__ float g_B [2][VF * NCOLS];             // weights k-major [k][c], tf32 bits
__device__ float g_w1[2][NH * VF];                // Wvn @ a1
__device__ float g_w2[2][NH * VF];                // Wvc @ a2
__device__ float g_s1[(size_t)N_NODES * NH];
__device__ float g_s2[(size_t)N_NODES * NH];
__device__ int   g_perm[2][N_NODES];
__device__ int   g_posb[N_NODES];                 // (pos<<1) | branch
__device__ int   g_cnt[2];

// ---------------- helpers ----------------------------------------------------
__device__ __forceinline__ uint32_t f2tf32(float x) {
    uint32_t r;
    asm("cvt.rna.tf32.f32 %0, %1;" : "=r"(r) : "f"(x));
    return r;
}
__device__ __forceinline__ void mma_tf32(float (&d)[4], const uint32_t (&a)[4],
                                         const uint32_t (&b)[2]) {
    asm volatile(
        "mma.sync.aligned.m16n8k8.row.col.f32.tf32.tf32.f32 "
        "{%0,%1,%2,%3}, {%4,%5,%6,%7}, {%8,%9}, {%0,%1,%2,%3};"
        : "+f"(d[0]), "+f"(d[1]), "+f"(d[2]), "+f"(d[3])
        : "r"(a[0]), "r"(a[1]), "r"(a[2]), "r"(a[3]), "r"(b[0]), "r"(b[1]));
}

// ---------------- prepack weights k-major (tf32-converted) ------------------
__global__ void prepack_kernel(const float* __restrict__ Wvc0, const float* __restrict__ Wvn0,
                               const float* __restrict__ Wvc1, const float* __restrict__ Wvn1) {
    int branch = blockIdx.y;
    const float* Wvc = branch ? Wvc1 : Wvc0;
    const float* Wvn = branch ? Wvn1 : Wvn0;
    int i = blockIdx.x * blockDim.x + threadIdx.x;
    if (i >= VF * NCOLS) return;
    int k = i / NCOLS, c = i % NCOLS;
    float v;
    if (c < ZC) v = Wvc[((size_t)(c / FILT) * VF + k) * FILT + (c % FILT)];
    else {
        int c2 = c - ZC;
        v = Wvn[((size_t)(c2 / FILT) * VF + k) * FILT + (c2 % FILT)];
    }
    g_B[branch][i] = __uint_as_float(f2tf32(v));
}

// ---------------- folded attention vectors ----------------------------------
__global__ void wvec_kernel(const float* __restrict__ Wvc0, const float* __restrict__ Wvn0,
                            const float* __restrict__ a0,
                            const float* __restrict__ Wvc1, const float* __restrict__ Wvn1,
                            const float* __restrict__ a1) {
    int branch = blockIdx.y;
    const float* Wvc = branch ? Wvc1 : Wvc0;
    const float* Wvn = branch ? Wvn1 : Wvn0;
    const float* a   = branch ? a1 : a0;
    int gw = (blockIdx.x * blockDim.x + threadIdx.x) >> 5;
    int lane = threadIdx.x & 31;
    if (gw >= NH * VF) return;
    int h = gw / VF, k = gw % VF;
    const float* wn = Wvn + ((size_t)h * VF + k) * FILT;
    const float* wc = Wvc + ((size_t)h * VF + k) * FILT;
    float v1 = wn[lane] * a[h * 128 + lane] + wn[lane + 32] * a[h * 128 + lane + 32];
    float v2 = wc[lane] * a[h * 128 + 64 + lane] + wc[lane + 32] * a[h * 128 + 96 + lane];
#pragma unroll
    for (int o = 16; o; o >>= 1) {
        v1 += __shfl_xor_sync(0xffffffffu, v1, o);
        v2 += __shfl_xor_sync(0xffffffffu, v2, o);
    }
    if (lane == 0) {
        g_w1[branch][h * VF + k] = v1;
        g_w2[branch][h * VF + k] = v2;
    }
}

// ---------------- compaction -------------------------------------------------
__global__ void reset_kernel() {
    if (threadIdx.x == 0) { g_cnt[0] = 0; g_cnt[1] = 0; }
}
__global__ void compact_kernel(const int* __restrict__ is_int) {
    int n = blockIdx.x * blockDim.x + threadIdx.x;
    if (n >= N_NODES) return;
    int b = (is_int[n] == 1) ? 0 : 1;
    int pos = atomicAdd(&g_cnt[b], 1);
    g_perm[b][pos] = n;
    g_posb[n] = (pos << 1) | b;
}

// ---------------- s1/s2 from raw vertices ------------------------------------
__global__ __launch_bounds__(256)
void s_kernel(const float* __restrict__ v_int, const float* __restrict__ v_nh,
              const int* __restrict__ is_int) {
    int n = (blockIdx.x * blockDim.x + threadIdx.x) >> 5;
    int lane = threadIdx.x & 31;
    if (n >= N_NODES) return;
    int b = (is_int[n] == 1) ? 0 : 1;
    const float* v = (b == 0 ? v_int : v_nh) + (size_t)n * VF;
    float4 x = *(const float4*)(v + lane * 4);
#pragma unroll
    for (int h = 0; h < NH; h++) {
        float4 w1 = *(const float4*)(g_w1[b] + h * VF + lane * 4);
        float4 w2 = *(const float4*)(g_w2[b] + h * VF + lane * 4);
        float v1 = x.x * w1.x + x.y * w1.y + x.z * w1.z + x.w * w1.w;
        float v2 = x.x * w2.x + x.y * w2.y + x.z * w2.z + x.w * w2.w;
#pragma unroll
        for (int o = 16; o; o >>= 1) {
            v1 += __shfl_xor_sync(0xffffffffu, v1, o);
            v2 += __shfl_xor_sync(0xffffffffu, v2, o);
        }
        if (lane == 0) {
            g_s1[(size_t)n * NH + h] = v1;
            g_s2[(size_t)n * NH + h] = v2;
        }
    }
}

// ---------------- TF32 mma.sync GEMM -----------------------------------------
// 256 threads / 8 warps. Tile: M=128 (compacted rows) x N=128 per slab, 3 slabs.
// Warp = 32(M) x 64(N) via 2x8 grid of m16n8k8 tiles.
#define AS_STRIDE 132           // conflict-free A fragment loads
#define BS_STRIDE 136           // conflict-free B fragment loads
#define GSMEM_BYTES ((128 * AS_STRIDE + 128 * BS_STRIDE) * 4)

__global__ void __launch_bounds__(256, 1)
gemm_kernel(const float* __restrict__ v_int, const float* __restrict__ v_nh) {
    extern __shared__ uint32_t sm[];
    uint32_t* As = sm;                         // [row][k]  row-major, stride 132
    uint32_t* Bs = sm + 128 * AS_STRIDE;       // [k][n]    k-major,  stride 136

    const int branch = blockIdx.y;
    const int cnt = g_cnt[branch];
    const int bm = blockIdx.x * 128;
    if (bm >= cnt) return;

    const int tid = threadIdx.x;
    const int lane = tid & 31;
    const int wid = tid >> 5;
    const int g = lane >> 2;                   // 0..7
    const int tg = lane & 3;                   // 0..3
    const int warp_m = wid & 3;                // 0..3 -> M offset 32*warp_m
    const int warp_n = wid >> 2;               // 0..1 -> N offset 64*warp_n

    // ---- load + convert A tile (128 rows x 128 k) ----
    {
        const int r = tid >> 1;
        const int ch = (tid & 1) * 64;
        const int grl = bm + r;
        const int nd = g_perm[branch][grl < cnt ? grl : cnt - 1];
        const float4* Ag = (const float4*)((branch ? v_nh : v_int) +
                                           (size_t)nd * VF + ch);
        uint32_t* dst = As + r * AS_STRIDE + ch;
#pragma unroll
        for (int j = 0; j < 16; j++) {
            float4 v = Ag[j];
            dst[j * 4 + 0] = f2tf32(v.x);
            dst[j * 4 + 1] = f2tf32(v.y);
            dst[j * 4 + 2] = f2tf32(v.z);
            dst[j * 4 + 3] = f2tf32(v.w);
        }
    }

#pragma unroll 1
    for (int s = 0; s < 3; s++) {
        __syncthreads();   // prior slab's reads done; (s=0) A stores pending too
        // ---- load B slab (128 k x 128 n), already tf32 bits ----
        {
            const int k = tid >> 1;
            const int ch = (tid & 1) * 64;
            const float4* Bg = (const float4*)(g_B[branch] +
                                               (size_t)k * NCOLS + s * 128 + ch);
            uint32_t* dst = Bs + k * BS_STRIDE + ch;
#pragma unroll
            for (int j = 0; j < 16; j++)
                *(float4*)(dst + j * 4) = Bg[j];
        }
        __syncthreads();

        float acc[2][8][4];
#pragma unroll
        for (int mt = 0; mt < 2; mt++)
#pragma unroll
            for (int nt = 0; nt < 8; nt++)
#pragma unroll
                for (int q = 0; q < 4; q++) acc[mt][nt][q] = 0.f;

        const int ar = warp_m * 32 + g;
        const int cb = warp_n * 64 + g;
#pragma unroll
        for (int k0 = 0; k0 < 128; k0 += 8) {
            uint32_t a[2][4];
#pragma unroll
            for (int mt = 0; mt < 2; mt++) {
                const uint32_t* ap = As + (ar + mt * 16) * AS_STRIDE + k0 + tg;
                a[mt][0] = ap[0];
                a[mt][1] = ap[8 * AS_STRIDE];
                a[mt][2] = ap[4];
                a[mt][3] = ap[8 * AS_STRIDE + 4];
            }
            uint32_t b[8][2];
            const uint32_t* bp0 = Bs + (k0 + tg) * BS_STRIDE + cb;
            const uint32_t* bp1 = bp0 + 4 * BS_STRIDE;
#pragma unroll
            for (int nt = 0; nt < 8; nt++) {
                b[nt][0] = bp0[nt * 8];
                b[nt][1] = bp1[nt * 8];
            }
#pragma unroll
            for (int mt = 0; mt < 2; mt++)
#pragma unroll
                for (int nt = 0; nt < 8; nt++)
                    mma_tf32(acc[mt][nt], a[mt], b[nt]);
        }

        // ---- epilogue: store to compacted Zc/Zn ----
        const int cbase = s * 128 + warp_n * 64;
        float* zb;
        int coff;
        if (cbase < ZC) { zb = g_Zc[branch]; coff = cbase; }
        else            { zb = g_Zn[branch]; coff = cbase - ZC; }
#pragma unroll
        for (int mt = 0; mt < 2; mt++) {
            const int r0 = warp_m * 32 + mt * 16 + g;
            const int gr0 = bm + r0, gr1 = gr0 + 8;
            float* row0 = zb + (size_t)gr0 * ZC + coff + 2 * tg;
            float* row1 = zb + (size_t)gr1 * ZC + coff + 2 * tg;
            const bool ok0 = gr0 < cnt, ok1 = gr1 < cnt;
#pragma unroll
            for (int nt = 0; nt < 8; nt++) {
                if (ok0) *(float2*)(row0 + nt * 8) =
                    make_float2(acc[mt][nt][0], acc[mt][nt][1]);
                if (ok1) *(float2*)(row1 + nt * 8) =
                    make_float2(acc[mt][nt][2], acc[mt][nt][3]);
            }
        }
    }
}

// ---------------- attention + aggregate + epilogue ---------------------------
__global__ __launch_bounds__(256)
void attn_kernel(const int* __restrict__ idx_int, const int* __restrict__ idx_nh,
                 const float* __restrict__ e_int, const float* __restrict__ e_nh,
                 const float* __restrict__ bv_int, const float* __restrict__ bv_nh,
                 float* __restrict__ out) {
    const int branch = blockIdx.y;
    const int* __restrict__ idx   = branch ? idx_nh : idx_int;
    const float* __restrict__ edg = branch ? e_nh : e_int;
    const float* __restrict__ bv  = branch ? bv_nh : bv_int;
    float* __restrict__ o = out + (size_t)branch * N_NODES * OUTC;

    int n = (blockIdx.x * blockDim.x + threadIdx.x) >> 5;
    int lane = threadIdx.x & 31;
    if (n >= N_NODES) return;

    const float* __restrict__ Zn = g_Zn[branch];
    const int pe_self = g_posb[n];
    const bool nact = (pe_self & 1) == branch;
    const int pos_self = pe_self >> 1;

    int myidx = -1;
    float myedge = 0.f;
    if (lane < KNBR) {
        myidx = idx[(size_t)n * KNBR + lane];
        myedge = edg[(size_t)n * KNBR + lane];
    }
    const bool has = (lane < KNBR) && (myidx >= 0);
    float part = has ? 1.f : 0.f;
    int gact = 0, posk = 0;
    if (has) {
        int pe = g_posb[myidx];
        gact = ((pe & 1) == branch) ? 1 : 0;
        posk = pe >> 1;
    }

    float cntp = part;
#pragma unroll
    for (int oo = 16; oo; oo >>= 1) cntp += __shfl_xor_sync(0xffffffffu, cntp, oo);
    const float invnorm = 1.f / fmaxf(cntp, 1.f);

    float s1k[NH] = {0.f, 0.f, 0.f};
    if (has && gact) {
#pragma unroll
        for (int h = 0; h < NH; h++) s1k[h] = g_s1[(size_t)myidx * NH + h];
    }
    float s2h[NH] = {0.f, 0.f, 0.f};
    if (nact && lane == 0) {
#pragma unroll
        for (int h = 0; h < NH; h++) s2h[h] = g_s2[(size_t)n * NH + h];
    }
#pragma unroll
    for (int h = 0; h < NH; h++) s2h[h] = __shfl_sync(0xffffffffu, s2h[h], 0);

#pragma unroll
    for (int h = 0; h < NH; h++) {
        float e = has ? (s1k[h] + s2h[h]) * myedge : 0.f;

        float emax = (lane < KNBR) ? e : -1e30f;
#pragma unroll
        for (int oo = 16; oo; oo >>= 1)
            emax = fmaxf(emax, __shfl_xor_sync(0xffffffffu, emax, oo));
        float p = (lane < KNBR) ? expf(e - emax) : 0.f;
        float psum = p;
#pragma unroll
        for (int oo = 16; oo; oo >>= 1) psum += __shfl_xor_sync(0xffffffffu, psum, oo);
        float w = (p / psum) * part * invnorm;

        float2 acc = make_float2(0.f, 0.f);
#pragma unroll
        for (int k = 0; k < KNBR; k++) {
            float wk = __shfl_sync(0xffffffffu, w, k);
            int gk = __shfl_sync(0xffffffffu, gact, k);
            int pk = __shfl_sync(0xffffffffu, posk, k);
            if (gk) {
                const float2 gv = *(const float2*)(Zn + (size_t)pk * ZC +
                                                   h * FILT + lane * 2);
                acc.x += wk * gv.x;
                acc.y += wk * gv.y;
            }
        }

        float2 zc = make_float2(0.f, 0.f);
        if (nact)
            zc = *(const float2*)(g_Zc[branch] + (size_t)pos_self * ZC +
                                  h * FILT + lane * 2);
        float b0 = bv[h * FILT + lane * 2];
        float b1 = bv[h * FILT + lane * 2 + 1];
        float2 o2;
        o2.x = fmaxf(zc.x + acc.x + b0, 0.f);
        o2.y = fmaxf(zc.y + acc.y + b1, 0.f);
        *(float2*)(o + (size_t)n * OUTC + h * FILT + lane * 2) = o2;
    }
}

// ---------------- launch ------------------------------------------------------
extern "C" void kernel_launch(void* const* d_in, const int* in_sizes, int n_in,
                              void* d_out, int out_size) {
    const float* vertices_int = (const float*)d_in[0];
    const float* vertices_nh  = (const float*)d_in[1];
    const int*   nh_indices   = (const int*)d_in[2];
    const int*   int_indices  = (const int*)d_in[3];
    const float* nh_edges     = (const float*)d_in[4];
    const float* int_edges    = (const float*)d_in[5];
    const int*   is_int       = (const int*)d_in[6];
    const float* Wvc_int      = (const float*)d_in[7];
    const float* Wvc_nh       = (const float*)d_in[8];
    const float* Wvn_int      = (const float*)d_in[9];
    const float* Wvn_nh       = (const float*)d_in[10];
    const float* bv_int       = (const float*)d_in[11];
    const float* bv_nh        = (const float*)d_in[12];
    const float* a_int        = (const float*)d_in[13];
    const float* a_nh         = (const float*)d_in[14];
    float* out = (float*)d_out;

    cudaFuncSetAttribute(gemm_kernel,
                         cudaFuncAttributeMaxDynamicSharedMemorySize, GSMEM_BYTES);

    reset_kernel<<<1, 32>>>();
    compact_kernel<<<(N_NODES + 255) / 256, 256>>>(is_int);

    dim3 pg((NCOLS * VF + 255) / 256, 2);
    prepack_kernel<<<pg, 256>>>(Wvc_int, Wvn_int, Wvc_nh, Wvn_nh);
    dim3 wg((NH * VF * 32 + 255) / 256, 2);
    wvec_kernel<<<wg, 256>>>(Wvc_int, Wvn_int, a_int, Wvc_nh, Wvn_nh, a_nh);

    const int WARP_BLOCKS = (N_NODES + 7) / 8;
    s_kernel<<<WARP_BLOCKS, 256>>>(vertices_int, vertices_nh, is_int);

    dim3 gg((N_NODES + 127) / 128, 2);
    gemm_kernel<<<gg, 256, GSMEM_BYTES>>>(vertices_int, vertices_nh);

    dim3 ag(WARP_BLOCKS, 2);
    attn_kernel<<<ag, 256>>>(int_indices, nh_indices, int_edges, nh_edges,
                             bv_int, bv_nh, out);
}

// round 5
// speedup vs baseline: 2.1810x; 1.1110x over previous
#include <cuda_runtime.h>
#include <cuda_bf16.h>
#include <cstdint>

#define N_NODES 100000
#define VF      128
#define FILT    64
#define NH      3
#define KNBR    10
#define ZC      192
#define NCOLS   384
#define OUTC    192

// ---------------- scratch (static device globals) --------------------------
__device__ float          g_Zc[2][(size_t)N_NODES * ZC];    // fp32, compacted
__device__ __nv_bfloat16  g_Znh[2][(size_t)N_NODES * ZC];   // bf16, compacted
__device__ float          g_B [2][VF * NCOLS];              // k-major, tf32 bits
__device__ float          g_w1[2][NH * VF];
__device__ float          g_w2[2][NH * VF];
__device__ float          g_s1[(size_t)N_NODES * NH];
__device__ float          g_s2[(size_t)N_NODES * NH];
__device__ int            g_perm[2][N_NODES];
__device__ int            g_posb[N_NODES];                  // (pos<<1) | branch
__device__ int            g_cnt[2];

// ---------------- helpers ----------------------------------------------------
__device__ __forceinline__ uint32_t f2tf32(float x) {
    uint32_t r;
    asm("cvt.rna.tf32.f32 %0, %1;" : "=r"(r) : "f"(x));
    return r;
}
__device__ __forceinline__ void mma_tf32(float (&d)[4], const uint32_t (&a)[4],
                                         const uint32_t (&b)[2]) {
    asm volatile(
        "mma.sync.aligned.m16n8k8.row.col.f32.tf32.tf32.f32 "
        "{%0,%1,%2,%3}, {%4,%5,%6,%7}, {%8,%9}, {%0,%1,%2,%3};"
        : "+f"(d[0]), "+f"(d[1]), "+f"(d[2]), "+f"(d[3])
        : "r"(a[0]), "r"(a[1]), "r"(a[2]), "r"(a[3]), "r"(b[0]), "r"(b[1]));
}
__device__ __forceinline__ uint32_t smem_u32(const void* p) {
    uint32_t a;
    asm("{ .reg .u64 t; cvta.to.shared.u64 t, %1; cvt.u32.u64 %0, t; }"
        : "=r"(a) : "l"(p));
    return a;
}
__device__ __forceinline__ void cp_async16(uint32_t saddr, const void* g) {
    asm volatile("cp.async.cg.shared.global [%0], [%1], 16;"
                 :: "r"(saddr), "l"(g) : "memory");
}
#define CP_COMMIT() asm volatile("cp.async.commit_group;" ::: "memory")
#define CP_WAIT(n)  asm volatile("cp.async.wait_group %0;" :: "n"(n) : "memory")
__device__ __forceinline__ uint32_t pack_bf16x2(float lo, float hi) {
    uint32_t r;
    asm("cvt.rn.bf16x2.f32 %0, %1, %2;" : "=r"(r) : "f"(hi), "f"(lo));
    return r;
}

// ---------------- prepack weights k-major (tf32) + counter reset -------------
__global__ void prepack_kernel(const float* __restrict__ Wvc0, const float* __restrict__ Wvn0,
                               const float* __restrict__ Wvc1, const float* __restrict__ Wvn1) {
    if (blockIdx.x == 0 && blockIdx.y == 0 && threadIdx.x == 0) {
        g_cnt[0] = 0;
        g_cnt[1] = 0;
    }
    int branch = blockIdx.y;
    const float* Wvc = branch ? Wvc1 : Wvc0;
    const float* Wvn = branch ? Wvn1 : Wvn0;
    int i = blockIdx.x * blockDim.x + threadIdx.x;
    if (i >= VF * NCOLS) return;
    int k = i / NCOLS, c = i % NCOLS;
    float v;
    if (c < ZC) v = Wvc[((size_t)(c / FILT) * VF + k) * FILT + (c % FILT)];
    else {
        int c2 = c - ZC;
        v = Wvn[((size_t)(c2 / FILT) * VF + k) * FILT + (c2 % FILT)];
    }
    g_B[branch][i] = __uint_as_float(f2tf32(v));
}

// ---------------- folded attention vectors -----------------------------------
__global__ void wvec_kernel(const float* __restrict__ Wvc0, const float* __restrict__ Wvn0,
                            const float* __restrict__ a0,
                            const float* __restrict__ Wvc1, const float* __restrict__ Wvn1,
                            const float* __restrict__ a1) {
    int branch = blockIdx.y;
    const float* Wvc = branch ? Wvc1 : Wvc0;
    const float* Wvn = branch ? Wvn1 : Wvn0;
    const float* a   = branch ? a1 : a0;
    int gw = (blockIdx.x * blockDim.x + threadIdx.x) >> 5;
    int lane = threadIdx.x & 31;
    if (gw >= NH * VF) return;
    int h = gw / VF, k = gw % VF;
    const float* wn = Wvn + ((size_t)h * VF + k) * FILT;
    const float* wc = Wvc + ((size_t)h * VF + k) * FILT;
    float v1 = wn[lane] * a[h * 128 + lane] + wn[lane + 32] * a[h * 128 + lane + 32];
    float v2 = wc[lane] * a[h * 128 + 64 + lane] + wc[lane + 32] * a[h * 128 + 96 + lane];
#pragma unroll
    for (int o = 16; o; o >>= 1) {
        v1 += __shfl_xor_sync(0xffffffffu, v1, o);
        v2 += __shfl_xor_sync(0xffffffffu, v2, o);
    }
    if (lane == 0) {
        g_w1[branch][h * VF + k] = v1;
        g_w2[branch][h * VF + k] = v2;
    }
}

// ---------------- compaction ---------------------------------------------------
__global__ void compact_kernel(const int* __restrict__ is_int) {
    int n = blockIdx.x * blockDim.x + threadIdx.x;
    if (n >= N_NODES) return;
    int b = (is_int[n] == 1) ? 0 : 1;
    int pos = atomicAdd(&g_cnt[b], 1);
    g_perm[b][pos] = n;
    g_posb[n] = (pos << 1) | b;
}

// ---------------- s1/s2 from raw vertices --------------------------------------
__global__ __launch_bounds__(256)
void s_kernel(const float* __restrict__ v_int, const float* __restrict__ v_nh,
              const int* __restrict__ is_int) {
    int n = (blockIdx.x * blockDim.x + threadIdx.x) >> 5;
    int lane = threadIdx.x & 31;
    if (n >= N_NODES) return;
    int b = (is_int[n] == 1) ? 0 : 1;
    const float* v = (b == 0 ? v_int : v_nh) + (size_t)n * VF;
    float4 x = *(const float4*)(v + lane * 4);
#pragma unroll
    for (int h = 0; h < NH; h++) {
        float4 w1 = *(const float4*)(g_w1[b] + h * VF + lane * 4);
        float4 w2 = *(const float4*)(g_w2[b] + h * VF + lane * 4);
        float v1 = x.x * w1.x + x.y * w1.y + x.z * w1.z + x.w * w1.w;
        float v2 = x.x * w2.x + x.y * w2.y + x.z * w2.z + x.w * w2.w;
#pragma unroll
        for (int o = 16; o; o >>= 1) {
            v1 += __shfl_xor_sync(0xffffffffu, v1, o);
            v2 += __shfl_xor_sync(0xffffffffu, v2, o);
        }
        if (lane == 0) {
            g_s1[(size_t)n * NH + h] = v1;
            g_s2[(size_t)n * NH + h] = v2;
        }
    }
}

// ---------------- TF32 mma.sync GEMM, cp.async double-buffered B ---------------
// 256 threads / 8 warps. Tile: M=128 x N=128 per slab, 3 slabs, K=128.
#define AS_STRIDE 132
#define BS_STRIDE 136
#define B_BUF_U32 (128 * BS_STRIDE)
#define GSMEM_BYTES ((128 * AS_STRIDE + 2 * B_BUF_U32) * 4)

__global__ void __launch_bounds__(256, 1)
gemm_kernel(const float* __restrict__ v_int, const float* __restrict__ v_nh) {
    extern __shared__ uint32_t sm[];
    uint32_t* As = sm;
    uint32_t* Bs0 = sm + 128 * AS_STRIDE;

    const int branch = blockIdx.y;
    const int cnt = g_cnt[branch];
    const int bm = blockIdx.x * 128;
    if (bm >= cnt) return;

    const int tid = threadIdx.x;
    const int lane = tid & 31;
    const int wid = tid >> 5;
    const int g = lane >> 2;
    const int tg = lane & 3;
    const int warp_m = wid & 3;
    const int warp_n = wid >> 2;

    const uint32_t sbB = smem_u32(Bs0);

    // ---- prefetch B slab 0 (buf0) and slab 1 (buf1) via cp.async ----
    {
        const int k = tid >> 1;
        const int ch = (tid & 1) * 64;
        const float* Bsrc = g_B[branch] + (size_t)k * NCOLS + ch;
        const uint32_t bdst = sbB + (uint32_t)(k * BS_STRIDE + ch) * 4u;
#pragma unroll
        for (int j = 0; j < 16; j++) cp_async16(bdst + j * 16, Bsrc + j * 4);
        CP_COMMIT();
#pragma unroll
        for (int j = 0; j < 16; j++)
            cp_async16(bdst + B_BUF_U32 * 4 + j * 16, Bsrc + 128 + j * 4);
        CP_COMMIT();
    }

    // ---- load + convert A tile (overlaps with B cp.async in flight) ----
    {
        const int r = tid >> 1;
        const int ch = (tid & 1) * 64;
        const int grl = bm + r;
        const int nd = g_perm[branch][grl < cnt ? grl : cnt - 1];
        const float4* Ag = (const float4*)((branch ? v_nh : v_int) +
                                           (size_t)nd * VF + ch);
        uint32_t* dst = As + r * AS_STRIDE + ch;
#pragma unroll
        for (int j = 0; j < 16; j++) {
            float4 v = Ag[j];
            dst[j * 4 + 0] = f2tf32(v.x);
            dst[j * 4 + 1] = f2tf32(v.y);
            dst[j * 4 + 2] = f2tf32(v.z);
            dst[j * 4 + 3] = f2tf32(v.w);
        }
    }

#pragma unroll 1
    for (int s = 0; s < 3; s++) {
        if (s < 2) { CP_WAIT(1); } else { CP_WAIT(0); }
        __syncthreads();

        const uint32_t* Bs = Bs0 + (s & 1) * B_BUF_U32;

        float acc[2][8][4];
#pragma unroll
        for (int mt = 0; mt < 2; mt++)
#pragma unroll
            for (int nt = 0; nt < 8; nt++)
#pragma unroll
                for (int q = 0; q < 4; q++) acc[mt][nt][q] = 0.f;

        const int ar = warp_m * 32 + g;
        const int cb = warp_n * 64 + g;
#pragma unroll
        for (int k0 = 0; k0 < 128; k0 += 8) {
            uint32_t a[2][4];
#pragma unroll
            for (int mt = 0; mt < 2; mt++) {
                const uint32_t* ap = As + (ar + mt * 16) * AS_STRIDE + k0 + tg;
                a[mt][0] = ap[0];
                a[mt][1] = ap[8 * AS_STRIDE];
                a[mt][2] = ap[4];
                a[mt][3] = ap[8 * AS_STRIDE + 4];
            }
            uint32_t b[8][2];
            const uint32_t* bp0 = Bs + (k0 + tg) * BS_STRIDE + cb;
            const uint32_t* bp1 = bp0 + 4 * BS_STRIDE;
#pragma unroll
            for (int nt = 0; nt < 8; nt++) {
                b[nt][0] = bp0[nt * 8];
                b[nt][1] = bp1[nt * 8];
            }
#pragma unroll
            for (int mt = 0; mt < 2; mt++)
#pragma unroll
                for (int nt = 0; nt < 8; nt++)
                    mma_tf32(acc[mt][nt], a[mt], b[nt]);
        }

        __syncthreads();   // all reads of this buffer finished

        if (s == 0) {      // prefetch slab 2 into buf0 (overlaps slab-1 compute)
            const int k = tid >> 1;
            const int ch = (tid & 1) * 64;
            const float* Bsrc = g_B[branch] + (size_t)k * NCOLS + 256 + ch;
            const uint32_t bdst = sbB + (uint32_t)(k * BS_STRIDE + ch) * 4u;
#pragma unroll
            for (int j = 0; j < 16; j++) cp_async16(bdst + j * 16, Bsrc + j * 4);
            CP_COMMIT();
        }

        // ---- epilogue ----
        const int cbase = s * 128 + warp_n * 64;
        if (cbase < ZC) {
            float* zb = g_Zc[branch];
            const int coff = cbase;
#pragma unroll
            for (int mt = 0; mt < 2; mt++) {
                const int r0 = warp_m * 32 + mt * 16 + g;
                const int gr0 = bm + r0, gr1 = gr0 + 8;
                float* row0 = zb + (size_t)gr0 * ZC + coff + 2 * tg;
                float* row1 = zb + (size_t)gr1 * ZC + coff + 2 * tg;
                const bool ok0 = gr0 < cnt, ok1 = gr1 < cnt;
#pragma unroll
                for (int nt = 0; nt < 8; nt++) {
                    if (ok0) *(float2*)(row0 + nt * 8) =
                        make_float2(acc[mt][nt][0], acc[mt][nt][1]);
                    if (ok1) *(float2*)(row1 + nt * 8) =
                        make_float2(acc[mt][nt][2], acc[mt][nt][3]);
                }
            }
        } else {
            __nv_bfloat16* zb = g_Znh[branch];
            const int coff = cbase - ZC;
#pragma unroll
            for (int mt = 0; mt < 2; mt++) {
                const int r0 = warp_m * 32 + mt * 16 + g;
                const int gr0 = bm + r0, gr1 = gr0 + 8;
                uint32_t* row0 = (uint32_t*)(zb + (size_t)gr0 * ZC + coff + 2 * tg);
                uint32_t* row1 = (uint32_t*)(zb + (size_t)gr1 * ZC + coff + 2 * tg);
                const bool ok0 = gr0 < cnt, ok1 = gr1 < cnt;
#pragma unroll
                for (int nt = 0; nt < 8; nt++) {
                    if (ok0) row0[nt * 4] = pack_bf16x2(acc[mt][nt][0], acc[mt][nt][1]);
                    if (ok1) row1[nt * 4] = pack_bf16x2(acc[mt][nt][2], acc[mt][nt][3]);
                }
            }
        }
    }
}

// ---------------- attention + aggregate + epilogue -----------------------------
__global__ __launch_bounds__(256)
void attn_kernel(const int* __restrict__ idx_int, const int* __restrict__ idx_nh,
                 const float* __restrict__ e_int, const float* __restrict__ e_nh,
                 const float* __restrict__ bv_int, const float* __restrict__ bv_nh,
                 float* __restrict__ out) {
    const int branch = blockIdx.y;
    const int* __restrict__ idx   = branch ? idx_nh : idx_int;
    const float* __restrict__ edg = branch ? e_nh : e_int;
    const float* __restrict__ bv  = branch ? bv_nh : bv_int;
    float* __restrict__ o = out + (size_t)branch * N_NODES * OUTC;

    int n = (blockIdx.x * blockDim.x + threadIdx.x) >> 5;
    int lane = threadIdx.x & 31;
    if (n >= N_NODES) return;

    const __nv_bfloat16* __restrict__ Zn = g_Znh[branch];
    const int pe_self = g_posb[n];
    const bool nact = (pe_self & 1) == branch;
    const int pos_self = pe_self >> 1;

    int myidx = -1;
    float myedge = 0.f;
    if (lane < KNBR) {
        myidx = idx[(size_t)n * KNBR + lane];
        myedge = edg[(size_t)n * KNBR + lane];
    }
    const bool has = (lane < KNBR) && (myidx >= 0);
    float part = has ? 1.f : 0.f;
    int gact = 0, posk = 0;
    if (has) {
        int pe = g_posb[myidx];
        gact = ((pe & 1) == branch) ? 1 : 0;
        posk = pe >> 1;
    }

    float cntp = part;
#pragma unroll
    for (int oo = 16; oo; oo >>= 1) cntp += __shfl_xor_sync(0xffffffffu, cntp, oo);
    const float invnorm = 1.f / fmaxf(cntp, 1.f);

    float s1k[NH] = {0.f, 0.f, 0.f};
    if (has && gact) {
#pragma unroll
        for (int h = 0; h < NH; h++) s1k[h] = g_s1[(size_t)myidx * NH + h];
    }
    float s2h[NH] = {0.f, 0.f, 0.f};
    if (nact && lane == 0) {
#pragma unroll
        for (int h = 0; h < NH; h++) s2h[h] = g_s2[(size_t)n * NH + h];
    }
#pragma unroll
    for (int h = 0; h < NH; h++) s2h[h] = __shfl_sync(0xffffffffu, s2h[h], 0);

#pragma unroll
    for (int h = 0; h < NH; h++) {
        float e = has ? (s1k[h] + s2h[h]) * myedge : 0.f;

        float emax = (lane < KNBR) ? e : -1e30f;
#pragma unroll
        for (int oo = 16; oo; oo >>= 1)
            emax = fmaxf(emax, __shfl_xor_sync(0xffffffffu, emax, oo));
        float p = (lane < KNBR) ? expf(e - emax) : 0.f;
        float psum = p;
#pragma unroll
        for (int oo = 16; oo; oo >>= 1) psum += __shfl_xor_sync(0xffffffffu, psum, oo);
        float w = (p / psum) * part * invnorm;

        float2 acc = make_float2(0.f, 0.f);
#pragma unroll
        for (int k = 0; k < KNBR; k++) {
            float wk = __shfl_sync(0xffffffffu, w, k);
            int gk = __shfl_sync(0xffffffffu, gact, k);
            int pk = __shfl_sync(0xffffffffu, posk, k);
            if (gk) {
                __nv_bfloat162 bb = *(const __nv_bfloat162*)(Zn + (size_t)pk * ZC +
                                                             h * FILT + lane * 2);
                float2 gv = __bfloat1622float2(bb);
                acc.x += wk * gv.x;
                acc.y += wk * gv.y;
            }
        }

        float2 zc = make_float2(0.f, 0.f);
        if (nact)
            zc = *(const float2*)(g_Zc[branch] + (size_t)pos_self * ZC +
                                  h * FILT + lane * 2);
        float b0 = bv[h * FILT + lane * 2];
        float b1 = bv[h * FILT + lane * 2 + 1];
        float2 o2;
        o2.x = fmaxf(zc.x + acc.x + b0, 0.f);
        o2.y = fmaxf(zc.y + acc.y + b1, 0.f);
        *(float2*)(o + (size_t)n * OUTC + h * FILT + lane * 2) = o2;
    }
}

// ---------------- launch ---------------------------------------------------------
extern "C" void kernel_launch(void* const* d_in, const int* in_sizes, int n_in,
                              void* d_out, int out_size) {
    const float* vertices_int = (const float*)d_in[0];
    const float* vertices_nh  = (const float*)d_in[1];
    const int*   nh_indices   = (const int*)d_in[2];
    const int*   int_indices  = (const int*)d_in[3];
    const float* nh_edges     = (const float*)d_in[4];
    const float* int_edges    = (const float*)d_in[5];
    const int*   is_int       = (const int*)d_in[6];
    const float* Wvc_int      = (const float*)d_in[7];
    const float* Wvc_nh       = (const float*)d_in[8];
    const float* Wvn_int      = (const float*)d_in[9];
    const float* Wvn_nh       = (const float*)d_in[10];
    const float* bv_int       = (const float*)d_in[11];
    const float* bv_nh        = (const float*)d_in[12];
    const float* a_int        = (const float*)d_in[13];
    const float* a_nh         = (const float*)d_in[14];
    float* out = (float*)d_out;

    cudaFuncSetAttribute(gemm_kernel,
                         cudaFuncAttributeMaxDynamicSharedMemorySize, GSMEM_BYTES);

    dim3 pg((NCOLS * VF + 255) / 256, 2);
    prepack_kernel<<<pg, 256>>>(Wvc_int, Wvn_int, Wvc_nh, Wvn_nh);
    dim3 wg((NH * VF * 32 + 255) / 256, 2);
    wvec_kernel<<<wg, 256>>>(Wvc_int, Wvn_int, a_int, Wvc_nh, Wvn_nh, a_nh);

    compact_kernel<<<(N_NODES + 255) / 256, 256>>>(is_int);

    const int WARP_BLOCKS = (N_NODES + 7) / 8;
    s_kernel<<<WARP_BLOCKS, 256>>>(vertices_int, vertices_nh, is_int);

    dim3 gg((N_NODES + 127) / 128, 2);
    gemm_kernel<<<gg, 256, GSMEM_BYTES>>>(vertices_int, vertices_nh);

    dim3 ag(WARP_BLOCKS, 2);
    attn_kernel<<<ag, 256>>>(int_indices, nh_indices, int_edges, nh_edges,
                             bv_int, bv_nh, out);
}

// round 6
// speedup vs baseline: 2.5577x; 1.1727x over previous
#include <cuda_runtime.h>
#include <cuda_bf16.h>
#include <cstdint>

#define N_NODES 100000
#define VF      128
#define FILT    64
#define NH      3
#define KNBR    10
#define ZC      192
#define NCOLS   384
#define OUTC    192

// ---------------- scratch (static device globals) --------------------------
__device__ float          g_Zc[2][(size_t)N_NODES * ZC];    // fp32, compacted
__device__ __nv_bfloat16  g_Znh[2][(size_t)N_NODES * ZC];   // bf16, compacted
__device__ float          g_B [2][VF * NCOLS];              // k-major, tf32 bits
__device__ float          g_w1[2][NH * VF];
__device__ float          g_w2[2][NH * VF];
__device__ float          g_s1[(size_t)N_NODES * NH];
__device__ float          g_s2[(size_t)N_NODES * NH];
__device__ int            g_perm[2][N_NODES];
__device__ int            g_posb[N_NODES];                  // (pos<<1) | branch
__device__ int            g_cnt[2];

// ---------------- helpers ----------------------------------------------------
__device__ __forceinline__ uint32_t f2tf32(float x) {
    uint32_t r;
    asm("cvt.rna.tf32.f32 %0, %1;" : "=r"(r) : "f"(x));
    return r;
}
__device__ __forceinline__ void mma_tf32(float (&d)[4], const uint32_t (&a)[4],
                                         const uint32_t (&b)[2]) {
    asm volatile(
        "mma.sync.aligned.m16n8k8.row.col.f32.tf32.tf32.f32 "
        "{%0,%1,%2,%3}, {%4,%5,%6,%7}, {%8,%9}, {%0,%1,%2,%3};"
        : "+f"(d[0]), "+f"(d[1]), "+f"(d[2]), "+f"(d[3])
        : "r"(a[0]), "r"(a[1]), "r"(a[2]), "r"(a[3]), "r"(b[0]), "r"(b[1]));
}
__device__ __forceinline__ uint32_t smem_u32(const void* p) {
    uint32_t a;
    asm("{ .reg .u64 t; cvta.to.shared.u64 t, %1; cvt.u32.u64 %0, t; }"
        : "=r"(a) : "l"(p));
    return a;
}
__device__ __forceinline__ void cp_async16(uint32_t saddr, const void* g) {
    asm volatile("cp.async.cg.shared.global [%0], [%1], 16;"
                 :: "r"(saddr), "l"(g) : "memory");
}
#define CP_COMMIT() asm volatile("cp.async.commit_group;" ::: "memory")
#define CP_WAIT(n)  asm volatile("cp.async.wait_group %0;" :: "n"(n) : "memory")
__device__ __forceinline__ uint32_t pack_bf16x2(float lo, float hi) {
    uint32_t r;
    asm("cvt.rn.bf16x2.f32 %0, %1, %2;" : "=r"(r) : "f"(hi), "f"(lo));
    return r;
}

// ---------------- reset (must precede atomic compaction each replay) ---------
__global__ void reset_kernel() {
    if (threadIdx.x == 0) { g_cnt[0] = 0; g_cnt[1] = 0; }
}

// ---------------- fused setup: prepack | wvec | compact -----------------------
// grid.x = 871: [0,384) prepack, [384,480) wvec, [480,871) compact
__global__ void setup_kernel(const float* __restrict__ Wvc0, const float* __restrict__ Wvn0,
                             const float* __restrict__ a0,
                             const float* __restrict__ Wvc1, const float* __restrict__ Wvn1,
                             const float* __restrict__ a1,
                             const int* __restrict__ is_int) {
    const int bid = blockIdx.x;
    if (bid < 384) {
        // ---- prepack weights k-major (tf32 bits) ----
        const int branch = bid >= 192;
        const float* Wvc = branch ? Wvc1 : Wvc0;
        const float* Wvn = branch ? Wvn1 : Wvn0;
        int i = (bid - branch * 192) * 256 + threadIdx.x;    // < 49152
        int k = i / NCOLS, c = i % NCOLS;
        float v;
        if (c < ZC) v = Wvc[((size_t)(c / FILT) * VF + k) * FILT + (c % FILT)];
        else {
            int c2 = c - ZC;
            v = Wvn[((size_t)(c2 / FILT) * VF + k) * FILT + (c2 % FILT)];
        }
        g_B[branch][i] = __uint_as_float(f2tf32(v));
    } else if (bid < 480) {
        // ---- folded attention vectors ----
        int w = (bid - 384) * 8 + (threadIdx.x >> 5);        // < 768
        int lane = threadIdx.x & 31;
        const int branch = w >= NH * VF;
        int gw = w - branch * NH * VF;
        int h = gw / VF, k = gw % VF;
        const float* Wvc = branch ? Wvc1 : Wvc0;
        const float* Wvn = branch ? Wvn1 : Wvn0;
        const float* a   = branch ? a1 : a0;
        const float* wn = Wvn + ((size_t)h * VF + k) * FILT;
        const float* wc = Wvc + ((size_t)h * VF + k) * FILT;
        float v1 = wn[lane] * a[h * 128 + lane] + wn[lane + 32] * a[h * 128 + lane + 32];
        float v2 = wc[lane] * a[h * 128 + 64 + lane] + wc[lane + 32] * a[h * 128 + 96 + lane];
#pragma unroll
        for (int o = 16; o; o >>= 1) {
            v1 += __shfl_xor_sync(0xffffffffu, v1, o);
            v2 += __shfl_xor_sync(0xffffffffu, v2, o);
        }
        if (lane == 0) {
            g_w1[branch][h * VF + k] = v1;
            g_w2[branch][h * VF + k] = v2;
        }
    } else {
        // ---- compaction ----
        int n = (bid - 480) * 256 + threadIdx.x;
        if (n >= N_NODES) return;
        int b = (is_int[n] == 1) ? 0 : 1;
        int pos = atomicAdd(&g_cnt[b], 1);
        g_perm[b][pos] = n;
        g_posb[n] = (pos << 1) | b;
    }
}

// ---------------- TF32 mma.sync GEMM + fused s1/s2 ---------------------------
#define AS_STRIDE 132
#define BS_STRIDE 136
#define B_BUF_U32 (128 * BS_STRIDE)
#define GSMEM_BYTES ((128 * AS_STRIDE + 2 * B_BUF_U32) * 4)

__global__ void __launch_bounds__(256, 1)
gemm_kernel(const float* __restrict__ v_int, const float* __restrict__ v_nh) {
    extern __shared__ uint32_t sm[];
    uint32_t* As = sm;
    uint32_t* Bs0 = sm + 128 * AS_STRIDE;

    const int branch = blockIdx.y;
    const int cnt = g_cnt[branch];
    const int bm = blockIdx.x * 128;
    if (bm >= cnt) return;

    const int tid = threadIdx.x;
    const int lane = tid & 31;
    const int wid = tid >> 5;
    const int g = lane >> 2;
    const int tg = lane & 3;
    const int warp_m = wid & 3;
    const int warp_n = wid >> 2;

    const uint32_t sbB = smem_u32(Bs0);

    // ---- prefetch B slab 0 (buf0) and slab 1 (buf1) via cp.async ----
    {
        const int k = tid >> 1;
        const int ch = (tid & 1) * 64;
        const float* Bsrc = g_B[branch] + (size_t)k * NCOLS + ch;
        const uint32_t bdst = sbB + (uint32_t)(k * BS_STRIDE + ch) * 4u;
#pragma unroll
        for (int j = 0; j < 16; j++) cp_async16(bdst + j * 16, Bsrc + j * 4);
        CP_COMMIT();
#pragma unroll
        for (int j = 0; j < 16; j++)
            cp_async16(bdst + B_BUF_U32 * 4 + j * 16, Bsrc + 128 + j * 4);
        CP_COMMIT();
    }

    // ---- load + convert A tile ----
    const int r_row = tid >> 1;
    const int grl = bm + r_row;
    const int nd = g_perm[branch][grl < cnt ? grl : cnt - 1];
    {
        const int ch = (tid & 1) * 64;
        const float4* Ag = (const float4*)((branch ? v_nh : v_int) +
                                           (size_t)nd * VF + ch);
        uint32_t* dst = As + r_row * AS_STRIDE + ch;
#pragma unroll
        for (int j = 0; j < 16; j++) {
            float4 v = Ag[j];
            dst[j * 4 + 0] = f2tf32(v.x);
            dst[j * 4 + 1] = f2tf32(v.y);
            dst[j * 4 + 2] = f2tf32(v.z);
            dst[j * 4 + 3] = f2tf32(v.w);
        }
    }

#pragma unroll 1
    for (int s = 0; s < 3; s++) {
        if (s < 2) { CP_WAIT(1); } else { CP_WAIT(0); }
        __syncthreads();

        const uint32_t* Bs = Bs0 + (s & 1) * B_BUF_U32;

        float acc[2][8][4];
#pragma unroll
        for (int mt = 0; mt < 2; mt++)
#pragma unroll
            for (int nt = 0; nt < 8; nt++)
#pragma unroll
                for (int q = 0; q < 4; q++) acc[mt][nt][q] = 0.f;

        const int ar = warp_m * 32 + g;
        const int cb = warp_n * 64 + g;
#pragma unroll
        for (int k0 = 0; k0 < 128; k0 += 8) {
            uint32_t a[2][4];
#pragma unroll
            for (int mt = 0; mt < 2; mt++) {
                const uint32_t* ap = As + (ar + mt * 16) * AS_STRIDE + k0 + tg;
                a[mt][0] = ap[0];
                a[mt][1] = ap[8 * AS_STRIDE];
                a[mt][2] = ap[4];
                a[mt][3] = ap[8 * AS_STRIDE + 4];
            }
            uint32_t b[8][2];
            const uint32_t* bp0 = Bs + (k0 + tg) * BS_STRIDE + cb;
            const uint32_t* bp1 = bp0 + 4 * BS_STRIDE;
#pragma unroll
            for (int nt = 0; nt < 8; nt++) {
                b[nt][0] = bp0[nt * 8];
                b[nt][1] = bp1[nt * 8];
            }
#pragma unroll
            for (int mt = 0; mt < 2; mt++)
#pragma unroll
                for (int nt = 0; nt < 8; nt++)
                    mma_tf32(acc[mt][nt], a[mt], b[nt]);
        }

        __syncthreads();   // all reads of this buffer finished

        if (s == 0) {      // prefetch slab 2 into buf0
            const int k = tid >> 1;
            const int ch = (tid & 1) * 64;
            const float* Bsrc = g_B[branch] + (size_t)k * NCOLS + 256 + ch;
            const uint32_t bdst = sbB + (uint32_t)(k * BS_STRIDE + ch) * 4u;
#pragma unroll
            for (int j = 0; j < 16; j++) cp_async16(bdst + j * 16, Bsrc + j * 4);
            CP_COMMIT();
        }

        // ---- epilogue ----
        const int cbase = s * 128 + warp_n * 64;
        if (cbase < ZC) {
            float* zb = g_Zc[branch];
            const int coff = cbase;
#pragma unroll
            for (int mt = 0; mt < 2; mt++) {
                const int r0 = warp_m * 32 + mt * 16 + g;
                const int gr0 = bm + r0, gr1 = gr0 + 8;
                float* row0 = zb + (size_t)gr0 * ZC + coff + 2 * tg;
                float* row1 = zb + (size_t)gr1 * ZC + coff + 2 * tg;
                const bool ok0 = gr0 < cnt, ok1 = gr1 < cnt;
#pragma unroll
                for (int nt = 0; nt < 8; nt++) {
                    if (ok0) *(float2*)(row0 + nt * 8) =
                        make_float2(acc[mt][nt][0], acc[mt][nt][1]);
                    if (ok1) *(float2*)(row1 + nt * 8) =
                        make_float2(acc[mt][nt][2], acc[mt][nt][3]);
                }
            }
        } else {
            __nv_bfloat16* zb = g_Znh[branch];
            const int coff = cbase - ZC;
#pragma unroll
            for (int mt = 0; mt < 2; mt++) {
                const int r0 = warp_m * 32 + mt * 16 + g;
                const int gr0 = bm + r0, gr1 = gr0 + 8;
                uint32_t* row0 = (uint32_t*)(zb + (size_t)gr0 * ZC + coff + 2 * tg);
                uint32_t* row1 = (uint32_t*)(zb + (size_t)gr1 * ZC + coff + 2 * tg);
                const bool ok0 = gr0 < cnt, ok1 = gr1 < cnt;
#pragma unroll
                for (int nt = 0; nt < 8; nt++) {
                    if (ok0) row0[nt * 4] = pack_bf16x2(acc[mt][nt][0], acc[mt][nt][1]);
                    if (ok1) row1[nt * 4] = pack_bf16x2(acc[mt][nt][2], acc[mt][nt][3]);
                }
            }
        }
    }

    // ---- fused s1/s2: 6 dot products per row against w1/w2 (A still in smem) ----
    // Stage w vectors into the retired B buffer (all compute reads done past the
    // collective barrier inside the s==2 iteration).
    float* wsv = (float*)Bs0;
    for (int i = tid; i < 6 * 128; i += 256) {
        int d = i >> 7, k = i & 127;
        wsv[d * AS_STRIDE + k] = (d < 3) ? g_w1[branch][d * 128 + k]
                                         : g_w2[branch][(d - 3) * 128 + k];
    }
    __syncthreads();
    {
        const int dset = (tid & 1) * 3;
        const uint32_t* arow = As + r_row * AS_STRIDE;
        const float* w0 = wsv + (dset + 0) * AS_STRIDE;
        const float* w1 = wsv + (dset + 1) * AS_STRIDE;
        const float* w2 = wsv + (dset + 2) * AS_STRIDE;
        float s0 = 0.f, s1 = 0.f, s2 = 0.f;
#pragma unroll 8
        for (int k = 0; k < 128; k++) {
            float a = __uint_as_float(arow[k]);
            s0 += a * w0[k];
            s1 += a * w1[k];
            s2 += a * w2[k];
        }
        if (grl < cnt) {
            float* dst = (tid & 1) ? &g_s2[(size_t)nd * NH] : &g_s1[(size_t)nd * NH];
            dst[0] = s0; dst[1] = s1; dst[2] = s2;
        }
    }
}

// ---------------- attention + aggregate + epilogue ---------------------------
// One warp per node. Softmax via shuffles; weights/positions staged in smem;
// gather: lanes 0..23 each own 8 contiguous bf16 (all 3 heads in one uint4/k).
__global__ __launch_bounds__(256)
void attn_kernel(const int* __restrict__ idx_int, const int* __restrict__ idx_nh,
                 const float* __restrict__ e_int, const float* __restrict__ e_nh,
                 const float* __restrict__ bv_int, const float* __restrict__ bv_nh,
                 float* __restrict__ out) {
    const int branch = blockIdx.y;
    const int* __restrict__ idx   = branch ? idx_nh : idx_int;
    const float* __restrict__ edg = branch ? e_nh : e_int;
    const float* __restrict__ bv  = branch ? bv_nh : bv_int;
    float* __restrict__ o = out + (size_t)branch * N_NODES * OUTC;

    __shared__ int   spos[8][KNBR];
    __shared__ float swt[8][NH][12];

    const int wslot = threadIdx.x >> 5;
    const int lane = threadIdx.x & 31;
    const int n = (blockIdx.x * blockDim.x + threadIdx.x) >> 5;
    if (n >= N_NODES) return;

    const int pe_self = g_posb[n];
    const bool nact = (pe_self & 1) == branch;
    const int pos_self = pe_self >> 1;

    int myidx = -1;
    float myedge = 0.f;
    if (lane < KNBR) {
        myidx = idx[(size_t)n * KNBR + lane];
        myedge = edg[(size_t)n * KNBR + lane];
    }
    const bool has = (lane < KNBR) && (myidx >= 0);
    float part = has ? 1.f : 0.f;
    int gact = 0, posk = 0;
    if (has) {
        int pe = g_posb[myidx];
        gact = ((pe & 1) == branch) ? 1 : 0;
        posk = pe >> 1;
    }
    if (lane < KNBR) spos[wslot][lane] = (has && gact) ? posk : -1;

    float cntp = part;
#pragma unroll
    for (int oo = 16; oo; oo >>= 1) cntp += __shfl_xor_sync(0xffffffffu, cntp, oo);
    const float invnorm = 1.f / fmaxf(cntp, 1.f);

    float s1k[NH] = {0.f, 0.f, 0.f};
    if (has && gact) {
#pragma unroll
        for (int h = 0; h < NH; h++) s1k[h] = g_s1[(size_t)myidx * NH + h];
    }
    float s2h[NH] = {0.f, 0.f, 0.f};
    if (nact && lane == 0) {
#pragma unroll
        for (int h = 0; h < NH; h++) s2h[h] = g_s2[(size_t)n * NH + h];
    }
#pragma unroll
    for (int h = 0; h < NH; h++) s2h[h] = __shfl_sync(0xffffffffu, s2h[h], 0);

#pragma unroll
    for (int h = 0; h < NH; h++) {
        float e = has ? (s1k[h] + s2h[h]) * myedge : 0.f;
        float emax = (lane < KNBR) ? e : -1e30f;
#pragma unroll
        for (int oo = 16; oo; oo >>= 1)
            emax = fmaxf(emax, __shfl_xor_sync(0xffffffffu, emax, oo));
        float p = (lane < KNBR) ? expf(e - emax) : 0.f;
        float psum = p;
#pragma unroll
        for (int oo = 16; oo; oo >>= 1) psum += __shfl_xor_sync(0xffffffffu, psum, oo);
        if (lane < KNBR) swt[wslot][h][lane] = (p / psum) * part * invnorm;
    }
    __syncwarp();

    // ---- gather: lanes 0..23 hold 8 contiguous channels of the 192-wide row ----
    const int myh = (lane < 24) ? (lane >> 3) : 0;
    const bool gl = lane < 24;
    float acc[8];
#pragma unroll
    for (int j = 0; j < 8; j++) acc[j] = 0.f;

    const uint4* __restrict__ Znb = (const uint4*)g_Znh[branch];
#pragma unroll 1
    for (int k = 0; k < KNBR; k++) {
        int pos = spos[wslot][k];
        if (pos < 0) continue;                    // uniform across warp
        if (gl) {
            float wk = swt[wslot][myh][k];
            uint4 v = Znb[(size_t)pos * 24 + lane];
            float2 f0 = __bfloat1622float2(*(__nv_bfloat162*)&v.x);
            float2 f1 = __bfloat1622float2(*(__nv_bfloat162*)&v.y);
            float2 f2 = __bfloat1622float2(*(__nv_bfloat162*)&v.z);
            float2 f3 = __bfloat1622float2(*(__nv_bfloat162*)&v.w);
            acc[0] += wk * f0.x; acc[1] += wk * f0.y;
            acc[2] += wk * f1.x; acc[3] += wk * f1.y;
            acc[4] += wk * f2.x; acc[5] += wk * f2.y;
            acc[6] += wk * f3.x; acc[7] += wk * f3.y;
        }
    }

    if (gl) {
        float4 zc0 = make_float4(0.f, 0.f, 0.f, 0.f), zc1 = zc0;
        if (nact) {
            const float4* zrow = (const float4*)(g_Zc[branch] +
                                                 (size_t)pos_self * ZC + lane * 8);
            zc0 = zrow[0];
            zc1 = zrow[1];
        }
        const float4* bvp = (const float4*)(bv + lane * 8);
        float4 b0 = bvp[0], b1 = bvp[1];
        float4 o0, o1;
        o0.x = fmaxf(acc[0] + zc0.x + b0.x, 0.f);
        o0.y = fmaxf(acc[1] + zc0.y + b0.y, 0.f);
        o0.z = fmaxf(acc[2] + zc0.z + b0.z, 0.f);
        o0.w = fmaxf(acc[3] + zc0.w + b0.w, 0.f);
        o1.x = fmaxf(acc[4] + zc1.x + b1.x, 0.f);
        o1.y = fmaxf(acc[5] + zc1.y + b1.y, 0.f);
        o1.z = fmaxf(acc[6] + zc1.z + b1.z, 0.f);
        o1.w = fmaxf(acc[7] + zc1.w + b1.w, 0.f);
        float4* op = (float4*)(o + (size_t)n * OUTC + lane * 8);
        op[0] = o0;
        op[1] = o1;
    }
}

// ---------------- launch ---------------------------------------------------------
extern "C" void kernel_launch(void* const* d_in, const int* in_sizes, int n_in,
                              void* d_out, int out_size) {
    const float* vertices_int = (const float*)d_in[0];
    const float* vertices_nh  = (const float*)d_in[1];
    const int*   nh_indices   = (const int*)d_in[2];
    const int*   int_indices  = (const int*)d_in[3];
    const float* nh_edges     = (const float*)d_in[4];
    const float* int_edges    = (const float*)d_in[5];
    const int*   is_int       = (const int*)d_in[6];
    const float* Wvc_int      = (const float*)d_in[7];
    const float* Wvc_nh       = (const float*)d_in[8];
    const float* Wvn_int      = (const float*)d_in[9];
    const float* Wvn_nh       = (const float*)d_in[10];
    const float* bv_int       = (const float*)d_in[11];
    const float* bv_nh        = (const float*)d_in[12];
    const float* a_int        = (const float*)d_in[13];
    const float* a_nh         = (const float*)d_in[14];
    float* out = (float*)d_out;

    cudaFuncSetAttribute(gemm_kernel,
                         cudaFuncAttributeMaxDynamicSharedMemorySize, GSMEM_BYTES);

    reset_kernel<<<1, 32>>>();
    setup_kernel<<<480 + (N_NODES + 255) / 256, 256>>>(
        Wvc_int, Wvn_int, a_int, Wvc_nh, Wvn_nh, a_nh, is_int);

    dim3 gg((N_NODES + 127) / 128, 2);
    gemm_kernel<<<gg, 256, GSMEM_BYTES>>>(vertices_int, vertices_nh);

    dim3 ag((N_NODES + 7) / 8, 2);
    attn_kernel<<<ag, 256>>>(int_indices, nh_indices, int_edges, nh_edges,
                             bv_int, bv_nh, out);
}

// round 7
// speedup vs baseline: 2.5999x; 1.0165x over previous
#include <cuda_runtime.h>
#include <cuda_bf16.h>
#include <cstdint>

#define N_NODES 100000
#define VF      128
#define FILT    64
#define NH      3
#define KNBR    10
#define ZC      192
#define NCOLS   384
#define OUTC    192

// ---------------- scratch (static device globals) --------------------------
__device__ float          g_Zc[2][(size_t)N_NODES * ZC];    // fp32, compacted
__device__ __nv_bfloat16  g_Znh[2][(size_t)N_NODES * ZC];   // bf16, compacted
__device__ float          g_B [2][VF * NCOLS];              // k-major, tf32 bits
__device__ float          g_w1[2][NH * VF];
__device__ float          g_w2[2][NH * VF];
__device__ float          g_s1[(size_t)N_NODES * NH];
__device__ float          g_s2[(size_t)N_NODES * NH];
__device__ int            g_perm[2][N_NODES];
__device__ int            g_posb[N_NODES];                  // (pos<<1) | branch
__device__ int            g_cnt[2];

// ---------------- helpers ----------------------------------------------------
__device__ __forceinline__ uint32_t f2tf32(float x) {
    uint32_t r;
    asm("cvt.rna.tf32.f32 %0, %1;" : "=r"(r) : "f"(x));
    return r;
}
__device__ __forceinline__ void mma_tf32(float (&d)[4], const uint32_t (&a)[4],
                                         const uint32_t (&b)[2]) {
    asm volatile(
        "mma.sync.aligned.m16n8k8.row.col.f32.tf32.tf32.f32 "
        "{%0,%1,%2,%3}, {%4,%5,%6,%7}, {%8,%9}, {%0,%1,%2,%3};"
        : "+f"(d[0]), "+f"(d[1]), "+f"(d[2]), "+f"(d[3])
        : "r"(a[0]), "r"(a[1]), "r"(a[2]), "r"(a[3]), "r"(b[0]), "r"(b[1]));
}
__device__ __forceinline__ uint32_t smem_u32(const void* p) {
    uint32_t a;
    asm("{ .reg .u64 t; cvta.to.shared.u64 t, %1; cvt.u32.u64 %0, t; }"
        : "=r"(a) : "l"(p));
    return a;
}
__device__ __forceinline__ void cp_async16(uint32_t saddr, const void* g) {
    asm volatile("cp.async.cg.shared.global [%0], [%1], 16;"
                 :: "r"(saddr), "l"(g) : "memory");
}
#define CP_COMMIT() asm volatile("cp.async.commit_group;" ::: "memory")
#define CP_WAIT(n)  asm volatile("cp.async.wait_group %0;" :: "n"(n) : "memory")
__device__ __forceinline__ uint32_t pack_bf16x2(float lo, float hi) {
    uint32_t r;
    asm("cvt.rn.bf16x2.f32 %0, %1, %2;" : "=r"(r) : "f"(hi), "f"(lo));
    return r;
}

// ---------------- reset (must precede atomic compaction each replay) ---------
__global__ void reset_kernel() {
    if (threadIdx.x == 0) { g_cnt[0] = 0; g_cnt[1] = 0; }
}

// ---------------- fused setup: prepack | wvec | compact -----------------------
__global__ void setup_kernel(const float* __restrict__ Wvc0, const float* __restrict__ Wvn0,
                             const float* __restrict__ a0,
                             const float* __restrict__ Wvc1, const float* __restrict__ Wvn1,
                             const float* __restrict__ a1,
                             const int* __restrict__ is_int) {
    const int bid = blockIdx.x;
    if (bid < 384) {
        // ---- prepack weights k-major (tf32 bits) ----
        const int branch = bid >= 192;
        const float* Wvc = branch ? Wvc1 : Wvc0;
        const float* Wvn = branch ? Wvn1 : Wvn0;
        int i = (bid - branch * 192) * 256 + threadIdx.x;    // < 49152
        int k = i / NCOLS, c = i % NCOLS;
        float v;
        if (c < ZC) v = Wvc[((size_t)(c / FILT) * VF + k) * FILT + (c % FILT)];
        else {
            int c2 = c - ZC;
            v = Wvn[((size_t)(c2 / FILT) * VF + k) * FILT + (c2 % FILT)];
        }
        g_B[branch][i] = __uint_as_float(f2tf32(v));
    } else if (bid < 480) {
        // ---- folded attention vectors ----
        int w = (bid - 384) * 8 + (threadIdx.x >> 5);        // < 768
        int lane = threadIdx.x & 31;
        const int branch = w >= NH * VF;
        int gw = w - branch * NH * VF;
        int h = gw / VF, k = gw % VF;
        const float* Wvc = branch ? Wvc1 : Wvc0;
        const float* Wvn = branch ? Wvn1 : Wvn0;
        const float* a   = branch ? a1 : a0;
        const float* wn = Wvn + ((size_t)h * VF + k) * FILT;
        const float* wc = Wvc + ((size_t)h * VF + k) * FILT;
        float v1 = wn[lane] * a[h * 128 + lane] + wn[lane + 32] * a[h * 128 + lane + 32];
        float v2 = wc[lane] * a[h * 128 + 64 + lane] + wc[lane + 32] * a[h * 128 + 96 + lane];
#pragma unroll
        for (int o = 16; o; o >>= 1) {
            v1 += __shfl_xor_sync(0xffffffffu, v1, o);
            v2 += __shfl_xor_sync(0xffffffffu, v2, o);
        }
        if (lane == 0) {
            g_w1[branch][h * VF + k] = v1;
            g_w2[branch][h * VF + k] = v2;
        }
    } else {
        // ---- compaction ----
        int n = (bid - 480) * 256 + threadIdx.x;
        if (n >= N_NODES) return;
        int b = (is_int[n] == 1) ? 0 : 1;
        int pos = atomicAdd(&g_cnt[b], 1);
        g_perm[b][pos] = n;
        g_posb[n] = (pos << 1) | b;
    }
}

// ---------------- TF32 mma.sync GEMM + fused s1/s2 ---------------------------
#define AS_STRIDE 132
#define BS_STRIDE 136
#define B_BUF_U32 (128 * BS_STRIDE)
#define GSMEM_BYTES ((128 * AS_STRIDE + 2 * B_BUF_U32) * 4)

__global__ void __launch_bounds__(256, 1)
gemm_kernel(const float* __restrict__ v_int, const float* __restrict__ v_nh) {
    extern __shared__ uint32_t sm[];
    uint32_t* As = sm;
    uint32_t* Bs0 = sm + 128 * AS_STRIDE;

    const int branch = blockIdx.y;
    const int cnt = g_cnt[branch];
    const int bm = blockIdx.x * 128;
    if (bm >= cnt) return;

    const int tid = threadIdx.x;
    const int lane = tid & 31;
    const int wid = tid >> 5;
    const int g = lane >> 2;
    const int tg = lane & 3;
    const int warp_m = wid & 3;
    const int warp_n = wid >> 2;

    const uint32_t sbB = smem_u32(Bs0);

    // ---- prefetch B slab 0 (buf0) and slab 1 (buf1) via cp.async ----
    {
        const int k = tid >> 1;
        const int ch = (tid & 1) * 64;
        const float* Bsrc = g_B[branch] + (size_t)k * NCOLS + ch;
        const uint32_t bdst = sbB + (uint32_t)(k * BS_STRIDE + ch) * 4u;
#pragma unroll
        for (int j = 0; j < 16; j++) cp_async16(bdst + j * 16, Bsrc + j * 4);
        CP_COMMIT();
#pragma unroll
        for (int j = 0; j < 16; j++)
            cp_async16(bdst + B_BUF_U32 * 4 + j * 16, Bsrc + 128 + j * 4);
        CP_COMMIT();
    }

    // ---- load + convert A tile ----
    const int r_row = tid >> 1;
    const int grl = bm + r_row;
    const int nd = g_perm[branch][grl < cnt ? grl : cnt - 1];
    {
        const int ch = (tid & 1) * 64;
        const float4* Ag = (const float4*)((branch ? v_nh : v_int) +
                                           (size_t)nd * VF + ch);
        uint32_t* dst = As + r_row * AS_STRIDE + ch;
#pragma unroll
        for (int j = 0; j < 16; j++) {
            float4 v = Ag[j];
            dst[j * 4 + 0] = f2tf32(v.x);
            dst[j * 4 + 1] = f2tf32(v.y);
            dst[j * 4 + 2] = f2tf32(v.z);
            dst[j * 4 + 3] = f2tf32(v.w);
        }
    }

#pragma unroll 1
    for (int s = 0; s < 3; s++) {
        if (s < 2) { CP_WAIT(1); } else { CP_WAIT(0); }
        __syncthreads();

        const uint32_t* Bs = Bs0 + (s & 1) * B_BUF_U32;

        float acc[2][8][4];
#pragma unroll
        for (int mt = 0; mt < 2; mt++)
#pragma unroll
            for (int nt = 0; nt < 8; nt++)
#pragma unroll
                for (int q = 0; q < 4; q++) acc[mt][nt][q] = 0.f;

        const int ar = warp_m * 32 + g;
        const int cb = warp_n * 64 + g;
#pragma unroll
        for (int k0 = 0; k0 < 128; k0 += 8) {
            uint32_t a[2][4];
#pragma unroll
            for (int mt = 0; mt < 2; mt++) {
                const uint32_t* ap = As + (ar + mt * 16) * AS_STRIDE + k0 + tg;
                a[mt][0] = ap[0];
                a[mt][1] = ap[8 * AS_STRIDE];
                a[mt][2] = ap[4];
                a[mt][3] = ap[8 * AS_STRIDE + 4];
            }
            uint32_t b[8][2];
            const uint32_t* bp0 = Bs + (k0 + tg) * BS_STRIDE + cb;
            const uint32_t* bp1 = bp0 + 4 * BS_STRIDE;
#pragma unroll
            for (int nt = 0; nt < 8; nt++) {
                b[nt][0] = bp0[nt * 8];
                b[nt][1] = bp1[nt * 8];
            }
#pragma unroll
            for (int mt = 0; mt < 2; mt++)
#pragma unroll
                for (int nt = 0; nt < 8; nt++)
                    mma_tf32(acc[mt][nt], a[mt], b[nt]);
        }

        __syncthreads();   // all reads of this buffer finished

        if (s == 0) {      // prefetch slab 2 into buf0
            const int k = tid >> 1;
            const int ch = (tid & 1) * 64;
            const float* Bsrc = g_B[branch] + (size_t)k * NCOLS + 256 + ch;
            const uint32_t bdst = sbB + (uint32_t)(k * BS_STRIDE + ch) * 4u;
#pragma unroll
            for (int j = 0; j < 16; j++) cp_async16(bdst + j * 16, Bsrc + j * 4);
            CP_COMMIT();
        }

        // ---- epilogue ----
        const int cbase = s * 128 + warp_n * 64;
        if (cbase < ZC) {
            float* zb = g_Zc[branch];
            const int coff = cbase;
#pragma unroll
            for (int mt = 0; mt < 2; mt++) {
                const int r0 = warp_m * 32 + mt * 16 + g;
                const int gr0 = bm + r0, gr1 = gr0 + 8;
                float* row0 = zb + (size_t)gr0 * ZC + coff + 2 * tg;
                float* row1 = zb + (size_t)gr1 * ZC + coff + 2 * tg;
                const bool ok0 = gr0 < cnt, ok1 = gr1 < cnt;
#pragma unroll
                for (int nt = 0; nt < 8; nt++) {
                    if (ok0) *(float2*)(row0 + nt * 8) =
                        make_float2(acc[mt][nt][0], acc[mt][nt][1]);
                    if (ok1) *(float2*)(row1 + nt * 8) =
                        make_float2(acc[mt][nt][2], acc[mt][nt][3]);
                }
            }
        } else {
            __nv_bfloat16* zb = g_Znh[branch];
            const int coff = cbase - ZC;
#pragma unroll
            for (int mt = 0; mt < 2; mt++) {
                const int r0 = warp_m * 32 + mt * 16 + g;
                const int gr0 = bm + r0, gr1 = gr0 + 8;
                uint32_t* row0 = (uint32_t*)(zb + (size_t)gr0 * ZC + coff + 2 * tg);
                uint32_t* row1 = (uint32_t*)(zb + (size_t)gr1 * ZC + coff + 2 * tg);
                const bool ok0 = gr0 < cnt, ok1 = gr1 < cnt;
#pragma unroll
                for (int nt = 0; nt < 8; nt++) {
                    if (ok0) row0[nt * 4] = pack_bf16x2(acc[mt][nt][0], acc[mt][nt][1]);
                    if (ok1) row1[nt * 4] = pack_bf16x2(acc[mt][nt][2], acc[mt][nt][3]);
                }
            }
        }
    }

    // ---- fused s1/s2 (A still in smem; w vectors staged in retired B buffer) --
    float* wsv = (float*)Bs0;
    for (int i = tid; i < 6 * 128; i += 256) {
        int d = i >> 7, k = i & 127;
        wsv[d * AS_STRIDE + k] = (d < 3) ? g_w1[branch][d * 128 + k]
                                         : g_w2[branch][(d - 3) * 128 + k];
    }
    __syncthreads();
    {
        const int dset = (tid & 1) * 3;
        const uint32_t* arow = As + r_row * AS_STRIDE;
        const float* w0 = wsv + (dset + 0) * AS_STRIDE;
        const float* w1 = wsv + (dset + 1) * AS_STRIDE;
        const float* w2 = wsv + (dset + 2) * AS_STRIDE;
        float s0 = 0.f, s1 = 0.f, s2 = 0.f;
#pragma unroll 8
        for (int k = 0; k < 128; k++) {
            float a = __uint_as_float(arow[k]);
            s0 += a * w0[k];
            s1 += a * w1[k];
            s2 += a * w2[k];
        }
        if (grl < cnt) {
            float* dst = (tid & 1) ? &g_s2[(size_t)nd * NH] : &g_s1[(size_t)nd * NH];
            dst[0] = s0; dst[1] = s1; dst[2] = s2;
        }
    }
}

// ---------------- attention + aggregate + epilogue ---------------------------
// One warp per node. Width-16 reductions (K=10), __expf, byte offsets staged in
// smem, gather lanes 0..23 each own 8 contiguous bf16 channels (uint4/k).
__global__ __launch_bounds__(256)
void attn_kernel(const int* __restrict__ idx_int, const int* __restrict__ idx_nh,
                 const float* __restrict__ e_int, const float* __restrict__ e_nh,
                 const float* __restrict__ bv_int, const float* __restrict__ bv_nh,
                 float* __restrict__ out) {
    const int branch = blockIdx.y;
    const int* __restrict__ idx   = branch ? idx_nh : idx_int;
    const float* __restrict__ edg = branch ? e_nh : e_int;
    const float* __restrict__ bv  = branch ? bv_nh : bv_int;
    float* __restrict__ o = out + (size_t)branch * N_NODES * OUTC;

    __shared__ int   soff[8][16];        // byte offset of neighbor row, or -1
    __shared__ float swt[8][NH][16];

    const int wslot = threadIdx.x >> 5;
    const int lane = threadIdx.x & 31;
    const int n = (blockIdx.x * blockDim.x + threadIdx.x) >> 5;
    if (n >= N_NODES) return;

    const int pe_self = g_posb[n];
    const bool nact = (pe_self & 1) == branch;
    const int pos_self = pe_self >> 1;

    int myidx = -1;
    float myedge = 0.f;
    if (lane < KNBR) {
        myidx = idx[(size_t)n * KNBR + lane];
        myedge = edg[(size_t)n * KNBR + lane];
    }
    const bool has = (lane < KNBR) && (myidx >= 0);
    float part = has ? 1.f : 0.f;
    int gact = 0, posk = 0;
    if (has) {
        int pe = g_posb[myidx];
        gact = ((pe & 1) == branch) ? 1 : 0;
        posk = pe >> 1;
    }
    if (lane < 16)
        soff[wslot][lane] = (has && gact) ? posk * (ZC * 2) : -1;

    // count over lanes 0..15 (width-16 reduction; lanes>=10 contribute 0)
    float cntp = part;
#pragma unroll
    for (int oo = 8; oo; oo >>= 1) cntp += __shfl_xor_sync(0xffffffffu, cntp, oo, 16);
    const float invnorm = 1.f / fmaxf(cntp, 1.f);

    float s1k[NH] = {0.f, 0.f, 0.f};
    if (has && gact) {
#pragma unroll
        for (int h = 0; h < NH; h++) s1k[h] = g_s1[(size_t)myidx * NH + h];
    }
    float s2h[NH] = {0.f, 0.f, 0.f};
    if (nact && lane == 0) {
#pragma unroll
        for (int h = 0; h < NH; h++) s2h[h] = g_s2[(size_t)n * NH + h];
    }
#pragma unroll
    for (int h = 0; h < NH; h++) s2h[h] = __shfl_sync(0xffffffffu, s2h[h], 0);

#pragma unroll
    for (int h = 0; h < NH; h++) {
        float e = has ? (s1k[h] + s2h[h]) * myedge : 0.f;
        float emax = (lane < KNBR) ? e : -1e30f;
#pragma unroll
        for (int oo = 8; oo; oo >>= 1)
            emax = fmaxf(emax, __shfl_xor_sync(0xffffffffu, emax, oo, 16));
        float p = (lane < KNBR) ? __expf(e - emax) : 0.f;
        float psum = p;
#pragma unroll
        for (int oo = 8; oo; oo >>= 1) psum += __shfl_xor_sync(0xffffffffu, psum, oo, 16);
        if (lane < KNBR) swt[wslot][h][lane] = (p / psum) * part * invnorm;
    }
    __syncwarp();

    // ---- gather ----
    const int myh = (lane < 24) ? (lane >> 3) : 0;
    const bool gl = lane < 24;
    float acc[8];
#pragma unroll
    for (int j = 0; j < 8; j++) acc[j] = 0.f;

    const char* __restrict__ Zb = (const char*)g_Znh[branch];
    const int lane16 = lane * 16;
#pragma unroll 2
    for (int k = 0; k < KNBR; k++) {
        int off = soff[wslot][k];
        if (gl && off >= 0) {
            float wk = swt[wslot][myh][k];
            uint4 v = *(const uint4*)(Zb + off + lane16);
            float2 f0 = __bfloat1622float2(*(__nv_bfloat162*)&v.x);
            float2 f1 = __bfloat1622float2(*(__nv_bfloat162*)&v.y);
            float2 f2 = __bfloat1622float2(*(__nv_bfloat162*)&v.z);
            float2 f3 = __bfloat1622float2(*(__nv_bfloat162*)&v.w);
            acc[0] += wk * f0.x; acc[1] += wk * f0.y;
            acc[2] += wk * f1.x; acc[3] += wk * f1.y;
            acc[4] += wk * f2.x; acc[5] += wk * f2.y;
            acc[6] += wk * f3.x; acc[7] += wk * f3.y;
        }
    }

    if (gl) {
        float4 zc0 = make_float4(0.f, 0.f, 0.f, 0.f), zc1 = zc0;
        if (nact) {
            const float4* zrow = (const float4*)(g_Zc[branch] +
                                                 (size_t)pos_self * ZC + lane * 8);
            zc0 = zrow[0];
            zc1 = zrow[1];
        }
        const float4* bvp = (const float4*)(bv + lane * 8);
        float4 b0 = bvp[0], b1 = bvp[1];
        float4 o0, o1;
        o0.x = fmaxf(acc[0] + zc0.x + b0.x, 0.f);
        o0.y = fmaxf(acc[1] + zc0.y + b0.y, 0.f);
        o0.z = fmaxf(acc[2] + zc0.z + b0.z, 0.f);
        o0.w = fmaxf(acc[3] + zc0.w + b0.w, 0.f);
        o1.x = fmaxf(acc[4] + zc1.x + b1.x, 0.f);
        o1.y = fmaxf(acc[5] + zc1.y + b1.y, 0.f);
        o1.z = fmaxf(acc[6] + zc1.z + b1.z, 0.f);
        o1.w = fmaxf(acc[7] + zc1.w + b1.w, 0.f);
        float4* op = (float4*)(o + (size_t)n * OUTC + lane * 8);
        op[0] = o0;
        op[1] = o1;
    }
}

// ---------------- launch ---------------------------------------------------------
extern "C" void kernel_launch(void* const* d_in, const int* in_sizes, int n_in,
                              void* d_out, int out_size) {
    const float* vertices_int = (const float*)d_in[0];
    const float* vertices_nh  = (const float*)d_in[1];
    const int*   nh_indices   = (const int*)d_in[2];
    const int*   int_indices  = (const int*)d_in[3];
    const float* nh_edges     = (const float*)d_in[4];
    const float* int_edges    = (const float*)d_in[5];
    const int*   is_int       = (const int*)d_in[6];
    const float* Wvc_int      = (const float*)d_in[7];
    const float* Wvc_nh       = (const float*)d_in[8];
    const float* Wvn_int      = (const float*)d_in[9];
    const float* Wvn_nh       = (const float*)d_in[10];
    const float* bv_int       = (const float*)d_in[11];
    const float* bv_nh        = (const float*)d_in[12];
    const float* a_int        = (const float*)d_in[13];
    const float* a_nh         = (const float*)d_in[14];
    float* out = (float*)d_out;

    cudaFuncSetAttribute(gemm_kernel,
                         cudaFuncAttributeMaxDynamicSharedMemorySize, GSMEM_BYTES);

    reset_kernel<<<1, 32>>>();
    setup_kernel<<<480 + (N_NODES + 255) / 256, 256>>>(
        Wvc_int, Wvn_int, a_int, Wvc_nh, Wvn_nh, a_nh, is_int);

    dim3 gg((N_NODES + 127) / 128, 2);
    gemm_kernel<<<gg, 256, GSMEM_BYTES>>>(vertices_int, vertices_nh);

    dim3 ag((N_NODES + 7) / 8, 2);
    attn_kernel<<<ag, 256>>>(int_indices, nh_indices, int_edges, nh_edges,
                             bv_int, bv_nh, out);
}

// round 8
// speedup vs baseline: 3.2215x; 1.2391x over previous
#include <cuda_runtime.h>
#include <cuda_fp16.h>
#include <cuda_bf16.h>
#include <cstdint>

#define N_NODES 100000
#define VF      128
#define FILT    64
#define NH      3
#define KNBR    10
#define ZC      192
#define NCOLS   384
#define OUTC    192

// ---------------- scratch (static device globals) --------------------------
__device__ float          g_Zc[2][(size_t)N_NODES * ZC];    // fp32, compacted
__device__ __nv_bfloat16  g_Znh[2][(size_t)N_NODES * ZC];   // bf16, compacted
__device__ uint32_t       g_Bh[2][(VF / 2) * NCOLS];        // fp16x2 packed [k2][c]
__device__ float          g_w1[2][NH * VF];
__device__ float          g_w2[2][NH * VF];
__device__ int4           g_meta[N_NODES];   // {(pos<<1)|b, s1h0, s1h1, s1h2}
__device__ float4         g_s2v[N_NODES];
__device__ int            g_perm[2][N_NODES];
__device__ int            g_posb[N_NODES];
__device__ int            g_cnt[2];

// ---------------- helpers ----------------------------------------------------
__device__ __forceinline__ void mma_f16(float (&d)[4], const uint32_t (&a)[4],
                                        const uint32_t (&b)[2]) {
    asm volatile(
        "mma.sync.aligned.m16n8k16.row.col.f32.f16.f16.f32 "
        "{%0,%1,%2,%3}, {%4,%5,%6,%7}, {%8,%9}, {%0,%1,%2,%3};"
        : "+f"(d[0]), "+f"(d[1]), "+f"(d[2]), "+f"(d[3])
        : "r"(a[0]), "r"(a[1]), "r"(a[2]), "r"(a[3]), "r"(b[0]), "r"(b[1]));
}
__device__ __forceinline__ uint32_t smem_u32(const void* p) {
    uint32_t a;
    asm("{ .reg .u64 t; cvta.to.shared.u64 t, %1; cvt.u32.u64 %0, t; }"
        : "=r"(a) : "l"(p));
    return a;
}
__device__ __forceinline__ void cp_async16(uint32_t saddr, const void* g) {
    asm volatile("cp.async.cg.shared.global [%0], [%1], 16;"
                 :: "r"(saddr), "l"(g) : "memory");
}
#define CP_COMMIT() asm volatile("cp.async.commit_group;" ::: "memory")
#define CP_WAIT(n)  asm volatile("cp.async.wait_group %0;" :: "n"(n) : "memory")
__device__ __forceinline__ uint32_t pack_bf16x2(float lo, float hi) {
    uint32_t r;
    asm("cvt.rn.bf16x2.f32 %0, %1, %2;" : "=r"(r) : "f"(hi), "f"(lo));
    return r;
}
__device__ __forceinline__ uint32_t pack_f16x2(float lo, float hi) {
    __half2 h = __floats2half2_rn(lo, hi);
    return *(uint32_t*)&h;
}

// ---------------- reset -------------------------------------------------------
__global__ void reset_kernel() {
    if (threadIdx.x == 0) { g_cnt[0] = 0; g_cnt[1] = 0; }
}

// ---------------- fused setup: prepack | wvec | compact -------------------------
// grid.x: [0,192) prepack fp16, [192,288) wvec, [288,...) compact
__global__ void setup_kernel(const float* __restrict__ Wvc0, const float* __restrict__ Wvn0,
                             const float* __restrict__ a0,
                             const float* __restrict__ Wvc1, const float* __restrict__ Wvn1,
                             const float* __restrict__ a1,
                             const int* __restrict__ is_int) {
    const int bid = blockIdx.x;
    if (bid < 192) {
        // ---- prepack weights as packed fp16 pairs along k: g_Bh[k2][c] ----
        const int branch = bid >= 96;
        const float* Wvc = branch ? Wvc1 : Wvc0;
        const float* Wvn = branch ? Wvn1 : Wvn0;
        int i = (bid - branch * 96) * 256 + threadIdx.x;     // < 24576
        int k2 = i / NCOLS, c = i % NCOLS;
        const float* W;
        int h, o;
        if (c < ZC) { W = Wvc; h = c / FILT; o = c % FILT; }
        else        { W = Wvn; h = (c - ZC) / FILT; o = (c - ZC) % FILT; }
        float v0 = W[((size_t)h * VF + 2 * k2) * FILT + o];
        float v1 = W[((size_t)h * VF + 2 * k2 + 1) * FILT + o];
        g_Bh[branch][i] = pack_f16x2(v0, v1);
    } else if (bid < 288) {
        // ---- folded attention vectors ----
        int w = (bid - 192) * 8 + (threadIdx.x >> 5);        // < 768
        int lane = threadIdx.x & 31;
        const int branch = w >= NH * VF;
        int gw = w - branch * NH * VF;
        int h = gw / VF, k = gw % VF;
        const float* Wvc = branch ? Wvc1 : Wvc0;
        const float* Wvn = branch ? Wvn1 : Wvn0;
        const float* a   = branch ? a1 : a0;
        const float* wn = Wvn + ((size_t)h * VF + k) * FILT;
        const float* wc = Wvc + ((size_t)h * VF + k) * FILT;
        float v1 = wn[lane] * a[h * 128 + lane] + wn[lane + 32] * a[h * 128 + lane + 32];
        float v2 = wc[lane] * a[h * 128 + 64 + lane] + wc[lane + 32] * a[h * 128 + 96 + lane];
#pragma unroll
        for (int o = 16; o; o >>= 1) {
            v1 += __shfl_xor_sync(0xffffffffu, v1, o);
            v2 += __shfl_xor_sync(0xffffffffu, v2, o);
        }
        if (lane == 0) {
            g_w1[branch][h * VF + k] = v1;
            g_w2[branch][h * VF + k] = v2;
        }
    } else {
        // ---- compaction ----
        int n = (bid - 288) * 256 + threadIdx.x;
        if (n >= N_NODES) return;
        int b = (is_int[n] == 1) ? 0 : 1;
        int pos = atomicAdd(&g_cnt[b], 1);
        g_perm[b][pos] = n;
        int pb = (pos << 1) | b;
        g_posb[n] = pb;
        g_meta[n].x = pb;
    }
}

// ---------------- fp16 mma.sync GEMM (m16n8k16) + fused s1/s2 -------------------
// 256 threads / 8 warps, 2 blocks/SM. Tile: M=128 x N=128/slab, 3 slabs, K=128.
// A in smem: half2 [row][k2], stride 68 u32. B: half2 [k2][n], stride 136 u32.
#define AS2 68
#define BS2 136
#define A_U32 (128 * AS2)
#define B_BUF_U32 (64 * BS2)
#define GSMEM_BYTES ((A_U32 + 2 * B_BUF_U32) * 4)

__global__ void __launch_bounds__(256, 2)
gemm_kernel(const float* __restrict__ v_int, const float* __restrict__ v_nh) {
    extern __shared__ uint32_t sm[];
    uint32_t* As = sm;
    uint32_t* Bs0 = sm + A_U32;

    const int branch = blockIdx.y;
    const int cnt = g_cnt[branch];
    const int bm = blockIdx.x * 128;
    if (bm >= cnt) return;

    const int tid = threadIdx.x;
    const int lane = tid & 31;
    const int wid = tid >> 5;
    const int g = lane >> 2;
    const int tg = lane & 3;
    const int warp_m = wid & 3;
    const int warp_n = wid >> 2;

    const uint32_t sbB = smem_u32(Bs0);

    // ---- prefetch B slab 0 and 1 via cp.async (rows k2=tid/4, 128B quarters) ----
    {
        const int k2 = tid >> 2;
        const int coff = (tid & 3) * 32;                     // u32 offset in row
        const uint32_t* Bsrc = g_Bh[branch] + (size_t)k2 * NCOLS + coff;
        const uint32_t bdst = sbB + (uint32_t)(k2 * BS2 + coff) * 4u;
#pragma unroll
        for (int j = 0; j < 8; j++) cp_async16(bdst + j * 16, Bsrc + j * 4);
        CP_COMMIT();
#pragma unroll
        for (int j = 0; j < 8; j++)
            cp_async16(bdst + B_BUF_U32 * 4 + j * 16, Bsrc + 128 + j * 4);
        CP_COMMIT();
    }

    // ---- load + convert A tile to fp16 pairs ----
    const int r_row = tid >> 1;
    const int grl = bm + r_row;
    const int nd = g_perm[branch][grl < cnt ? grl : cnt - 1];
    {
        const int ch2 = (tid & 1) * 32;                      // half2 offset
        const float4* Ag = (const float4*)((branch ? v_nh : v_int) +
                                           (size_t)nd * VF + ch2 * 2);
        uint2* dst = (uint2*)(As + r_row * AS2 + ch2);
#pragma unroll
        for (int j = 0; j < 16; j++) {
            float4 v = Ag[j];
            dst[j] = make_uint2(pack_f16x2(v.x, v.y), pack_f16x2(v.z, v.w));
        }
    }

#pragma unroll 1
    for (int s = 0; s < 3; s++) {
        if (s < 2) { CP_WAIT(1); } else { CP_WAIT(0); }
        __syncthreads();

        const uint32_t* Bs = Bs0 + (s & 1) * B_BUF_U32;

        float acc[2][8][4];
#pragma unroll
        for (int mt = 0; mt < 2; mt++)
#pragma unroll
            for (int nt = 0; nt < 8; nt++)
#pragma unroll
                for (int q = 0; q < 4; q++) acc[mt][nt][q] = 0.f;

        const int ar = warp_m * 32 + g;
        const int cb = warp_n * 64 + g;
#pragma unroll
        for (int k2_0 = 0; k2_0 < 64; k2_0 += 8) {          // K=16 per iter
            uint32_t a[2][4];
#pragma unroll
            for (int mt = 0; mt < 2; mt++) {
                const uint32_t* ap = As + (ar + mt * 16) * AS2 + k2_0 + tg;
                a[mt][0] = ap[0];
                a[mt][1] = ap[8 * AS2];
                a[mt][2] = ap[4];
                a[mt][3] = ap[8 * AS2 + 4];
            }
            uint32_t b[8][2];
            const uint32_t* bp0 = Bs + (k2_0 + tg) * BS2 + cb;
            const uint32_t* bp1 = bp0 + 4 * BS2;
#pragma unroll
            for (int nt = 0; nt < 8; nt++) {
                b[nt][0] = bp0[nt * 8];
                b[nt][1] = bp1[nt * 8];
            }
#pragma unroll
            for (int mt = 0; mt < 2; mt++)
#pragma unroll
                for (int nt = 0; nt < 8; nt++)
                    mma_f16(acc[mt][nt], a[mt], b[nt]);
        }

        __syncthreads();

        if (s == 0) {      // prefetch slab 2 into buf0
            const int k2 = tid >> 2;
            const int coff = (tid & 3) * 32;
            const uint32_t* Bsrc = g_Bh[branch] + (size_t)k2 * NCOLS + 256 + coff;
            const uint32_t bdst = sbB + (uint32_t)(k2 * BS2 + coff) * 4u;
#pragma unroll
            for (int j = 0; j < 8; j++) cp_async16(bdst + j * 16, Bsrc + j * 4);
            CP_COMMIT();
        }

        // ---- epilogue ----
        const int cbase = s * 128 + warp_n * 64;
        if (cbase < ZC) {
            float* zb = g_Zc[branch];
            const int coff = cbase;
#pragma unroll
            for (int mt = 0; mt < 2; mt++) {
                const int r0 = warp_m * 32 + mt * 16 + g;
                const int gr0 = bm + r0, gr1 = gr0 + 8;
                float* row0 = zb + (size_t)gr0 * ZC + coff + 2 * tg;
                float* row1 = zb + (size_t)gr1 * ZC + coff + 2 * tg;
                const bool ok0 = gr0 < cnt, ok1 = gr1 < cnt;
#pragma unroll
                for (int nt = 0; nt < 8; nt++) {
                    if (ok0) *(float2*)(row0 + nt * 8) =
                        make_float2(acc[mt][nt][0], acc[mt][nt][1]);
                    if (ok1) *(float2*)(row1 + nt * 8) =
                        make_float2(acc[mt][nt][2], acc[mt][nt][3]);
                }
            }
        } else {
            __nv_bfloat16* zb = g_Znh[branch];
            const int coff = cbase - ZC;
#pragma unroll
            for (int mt = 0; mt < 2; mt++) {
                const int r0 = warp_m * 32 + mt * 16 + g;
                const int gr0 = bm + r0, gr1 = gr0 + 8;
                uint32_t* row0 = (uint32_t*)(zb + (size_t)gr0 * ZC + coff + 2 * tg);
                uint32_t* row1 = (uint32_t*)(zb + (size_t)gr1 * ZC + coff + 2 * tg);
                const bool ok0 = gr0 < cnt, ok1 = gr1 < cnt;
#pragma unroll
                for (int nt = 0; nt < 8; nt++) {
                    if (ok0) row0[nt * 4] = pack_bf16x2(acc[mt][nt][0], acc[mt][nt][1]);
                    if (ok1) row1[nt * 4] = pack_bf16x2(acc[mt][nt][2], acc[mt][nt][3]);
                }
            }
        }
    }

    // ---- fused s1/s2 from fp16 A tile (w vectors staged in retired B buffer) ----
    float* wsv = (float*)Bs0;
    for (int i = tid; i < 6 * 128; i += 256) {
        int d = i >> 7, k = i & 127;
        wsv[d * 132 + k] = (d < 3) ? g_w1[branch][d * 128 + k]
                                   : g_w2[branch][(d - 3) * 128 + k];
    }
    __syncthreads();
    {
        const int dset = (tid & 1) * 3;
        const __half2* arow = (const __half2*)(As + r_row * AS2);
        const float* w0 = wsv + (dset + 0) * 132;
        const float* w1 = wsv + (dset + 1) * 132;
        const float* w2 = wsv + (dset + 2) * 132;
        float s0 = 0.f, s1 = 0.f, s2 = 0.f;
#pragma unroll 8
        for (int k2 = 0; k2 < 64; k2++) {
            float2 av = __half22float2(arow[k2]);
            s0 += av.x * w0[2 * k2] + av.y * w0[2 * k2 + 1];
            s1 += av.x * w1[2 * k2] + av.y * w1[2 * k2 + 1];
            s2 += av.x * w2[2 * k2] + av.y * w2[2 * k2 + 1];
        }
        if (grl < cnt) {
            if (tid & 1) {
                g_s2v[nd] = make_float4(s0, s1, s2, 0.f);
            } else {
                float* mp = (float*)&g_meta[nd];
                mp[1] = s0; mp[2] = s1; mp[3] = s2;
            }
        }
    }
}

// ---------------- attention + aggregate + epilogue ---------------------------
__global__ __launch_bounds__(256)
void attn_kernel(const int* __restrict__ idx_int, const int* __restrict__ idx_nh,
                 const float* __restrict__ e_int, const float* __restrict__ e_nh,
                 const float* __restrict__ bv_int, const float* __restrict__ bv_nh,
                 float* __restrict__ out) {
    const int branch = blockIdx.y;
    const int* __restrict__ idx   = branch ? idx_nh : idx_int;
    const float* __restrict__ edg = branch ? e_nh : e_int;
    const float* __restrict__ bv  = branch ? bv_nh : bv_int;
    float* __restrict__ o = out + (size_t)branch * N_NODES * OUTC;

    __shared__ int   soff[8][16];
    __shared__ float swt[8][NH][16];

    const int wslot = threadIdx.x >> 5;
    const int lane = threadIdx.x & 31;
    const int n = (blockIdx.x * blockDim.x + threadIdx.x) >> 5;
    if (n >= N_NODES) return;

    const int pe_self = g_posb[n];
    const bool nact = (pe_self & 1) == branch;
    const int pos_self = pe_self >> 1;

    int myidx = -1;
    float myedge = 0.f;
    if (lane < KNBR) {
        myidx = idx[(size_t)n * KNBR + lane];
        myedge = edg[(size_t)n * KNBR + lane];
    }
    const bool has = (lane < KNBR) && (myidx >= 0);
    float part = has ? 1.f : 0.f;

    // packed neighbor metadata: one uint4 gives activity + pos + 3 s1 values
    int gact = 0, posk = 0;
    float s1k[NH] = {0.f, 0.f, 0.f};
    if (has) {
        int4 m = g_meta[myidx];
        gact = ((m.x & 1) == branch) ? 1 : 0;
        posk = m.x >> 1;
        if (gact) {
            s1k[0] = __int_as_float(m.y);
            s1k[1] = __int_as_float(m.z);
            s1k[2] = __int_as_float(m.w);
        }
    }
    if (lane < 16)
        soff[wslot][lane] = (has && gact) ? posk * (ZC * 2) : -1;

    float cntp = part;
#pragma unroll
    for (int oo = 8; oo; oo >>= 1) cntp += __shfl_xor_sync(0xffffffffu, cntp, oo, 16);
    const float invnorm = 1.f / fmaxf(cntp, 1.f);

    float s2h[NH] = {0.f, 0.f, 0.f};
    if (nact && lane == 0) {
        float4 sv = g_s2v[n];
        s2h[0] = sv.x; s2h[1] = sv.y; s2h[2] = sv.z;
    }
#pragma unroll
    for (int h = 0; h < NH; h++) s2h[h] = __shfl_sync(0xffffffffu, s2h[h], 0);

#pragma unroll
    for (int h = 0; h < NH; h++) {
        float e = has ? (s1k[h] + s2h[h]) * myedge : 0.f;
        float emax = (lane < KNBR) ? e : -1e30f;
#pragma unroll
        for (int oo = 8; oo; oo >>= 1)
            emax = fmaxf(emax, __shfl_xor_sync(0xffffffffu, emax, oo, 16));
        float p = (lane < KNBR) ? __expf(e - emax) : 0.f;
        float psum = p;
#pragma unroll
        for (int oo = 8; oo; oo >>= 1) psum += __shfl_xor_sync(0xffffffffu, psum, oo, 16);
        float rs = __fdividef(invnorm, psum);
        if (lane < KNBR) swt[wslot][h][lane] = p * rs * part;
    }
    __syncwarp();

    // ---- gather: lanes 0..23 own 8 contiguous bf16 channels (uint4 per k) ----
    const int myh = (lane < 24) ? (lane >> 3) : 0;
    const bool gl = lane < 24;
    float acc[8];
#pragma unroll
    for (int j = 0; j < 8; j++) acc[j] = 0.f;

    const char* __restrict__ Zb = (const char*)g_Znh[branch];
    const int lane16 = lane * 16;
#pragma unroll 2
    for (int k = 0; k < KNBR; k++) {
        int off = soff[wslot][k];
        if (gl && off >= 0) {
            float wk = swt[wslot][myh][k];
            uint4 v = *(const uint4*)(Zb + off + lane16);
            float2 f0 = __bfloat1622float2(*(__nv_bfloat162*)&v.x);
            float2 f1 = __bfloat1622float2(*(__nv_bfloat162*)&v.y);
            float2 f2 = __bfloat1622float2(*(__nv_bfloat162*)&v.z);
            float2 f3 = __bfloat1622float2(*(__nv_bfloat162*)&v.w);
            acc[0] += wk * f0.x; acc[1] += wk * f0.y;
            acc[2] += wk * f1.x; acc[3] += wk * f1.y;
            acc[4] += wk * f2.x; acc[5] += wk * f2.y;
            acc[6] += wk * f3.x; acc[7] += wk * f3.y;
        }
    }

    if (gl) {
        float4 zc0 = make_float4(0.f, 0.f, 0.f, 0.f), zc1 = zc0;
        if (nact) {
            const float4* zrow = (const float4*)(g_Zc[branch] +
                                                 (size_t)pos_self * ZC + lane * 8);
            zc0 = zrow[0];
            zc1 = zrow[1];
        }
        const float4* bvp = (const float4*)(bv + lane * 8);
        float4 b0 = bvp[0], b1 = bvp[1];
        float4 o0, o1;
        o0.x = fmaxf(acc[0] + zc0.x + b0.x, 0.f);
        o0.y = fmaxf(acc[1] + zc0.y + b0.y, 0.f);
        o0.z = fmaxf(acc[2] + zc0.z + b0.z, 0.f);
        o0.w = fmaxf(acc[3] + zc0.w + b0.w, 0.f);
        o1.x = fmaxf(acc[4] + zc1.x + b1.x, 0.f);
        o1.y = fmaxf(acc[5] + zc1.y + b1.y, 0.f);
        o1.z = fmaxf(acc[6] + zc1.z + b1.z, 0.f);
        o1.w = fmaxf(acc[7] + zc1.w + b1.w, 0.f);
        float4* op = (float4*)(o + (size_t)n * OUTC + lane * 8);
        op[0] = o0;
        op[1] = o1;
    }
}

// ---------------- launch ---------------------------------------------------------
extern "C" void kernel_launch(void* const* d_in, const int* in_sizes, int n_in,
                              void* d_out, int out_size) {
    const float* vertices_int = (const float*)d_in[0];
    const float* vertices_nh  = (const float*)d_in[1];
    const int*   nh_indices   = (const int*)d_in[2];
    const int*   int_indices  = (const int*)d_in[3];
    const float* nh_edges     = (const float*)d_in[4];
    const float* int_edges    = (const float*)d_in[5];
    const int*   is_int       = (const int*)d_in[6];
    const float* Wvc_int      = (const float*)d_in[7];
    const float* Wvc_nh       = (const float*)d_in[8];
    const float* Wvn_int      = (const float*)d_in[9];
    const float* Wvn_nh       = (const float*)d_in[10];
    const float* bv_int       = (const float*)d_in[11];
    const float* bv_nh        = (const float*)d_in[12];
    const float* a_int        = (const float*)d_in[13];
    const float* a_nh         = (const float*)d_in[14];
    float* out = (float*)d_out;

    cudaFuncSetAttribute(gemm_kernel,
                         cudaFuncAttributeMaxDynamicSharedMemorySize, GSMEM_BYTES);

    reset_kernel<<<1, 32>>>();
    setup_kernel<<<288 + (N_NODES + 255) / 256, 256>>>(
        Wvc_int, Wvn_int, a_int, Wvc_nh, Wvn_nh, a_nh, is_int);

    dim3 gg((N_NODES + 127) / 128, 2);
    gemm_kernel<<<gg, 256, GSMEM_BYTES>>>(vertices_int, vertices_nh);

    dim3 ag((N_NODES + 7) / 8, 2);
    attn_kernel<<<ag, 256>>>(int_indices, nh_indices, int_edges, nh_edges,
                             bv_int, bv_nh, out);
}

// round 9
// speedup vs baseline: 3.3635x; 1.0441x over previous
#include <cuda_runtime.h>
#include <cuda_fp16.h>
#include <cuda_bf16.h>
#include <cstdint>

#define N_NODES 100000
#define VF      128
#define FILT    64
#define NH      3
#define KNBR    10
#define ZC      192
#define NCOLS   384
#define OUTC    192

// ---------------- scratch (static device globals) --------------------------
__device__ float          g_Zc[2][(size_t)N_NODES * ZC];    // fp32, compacted
__device__ __nv_bfloat16  g_Znh[2][(size_t)N_NODES * ZC];   // bf16, compacted
__device__ uint32_t       g_Bh[2][(VF / 2) * NCOLS];        // fp16x2 packed [k2][c]
__device__ float          g_w1[2][NH * VF];
__device__ float          g_w2[2][NH * VF];
__device__ int4           g_meta[N_NODES];   // {(pos<<1)|b, s1h0, s1h1, s1h2}
__device__ float4         g_s2v[N_NODES];    // {s2h0, s2h1, s2h2, bits((pos<<1)|b)}
__device__ int            g_perm[2][N_NODES];
__device__ int            g_cnt[2];

// ---------------- helpers ----------------------------------------------------
__device__ __forceinline__ void mma_f16(float (&d)[4], const uint32_t (&a)[4],
                                        const uint32_t (&b)[2]) {
    asm volatile(
        "mma.sync.aligned.m16n8k16.row.col.f32.f16.f16.f32 "
        "{%0,%1,%2,%3}, {%4,%5,%6,%7}, {%8,%9}, {%0,%1,%2,%3};"
        : "+f"(d[0]), "+f"(d[1]), "+f"(d[2]), "+f"(d[3])
        : "r"(a[0]), "r"(a[1]), "r"(a[2]), "r"(a[3]), "r"(b[0]), "r"(b[1]));
}
__device__ __forceinline__ uint32_t smem_u32(const void* p) {
    uint32_t a;
    asm("{ .reg .u64 t; cvta.to.shared.u64 t, %1; cvt.u32.u64 %0, t; }"
        : "=r"(a) : "l"(p));
    return a;
}
__device__ __forceinline__ void cp_async16(uint32_t saddr, const void* g) {
    asm volatile("cp.async.cg.shared.global [%0], [%1], 16;"
                 :: "r"(saddr), "l"(g) : "memory");
}
#define CP_COMMIT() asm volatile("cp.async.commit_group;" ::: "memory")
#define CP_WAIT(n)  asm volatile("cp.async.wait_group %0;" :: "n"(n) : "memory")
__device__ __forceinline__ uint32_t pack_bf16x2(float lo, float hi) {
    uint32_t r;
    asm("cvt.rn.bf16x2.f32 %0, %1, %2;" : "=r"(r) : "f"(hi), "f"(lo));
    return r;
}
__device__ __forceinline__ uint32_t pack_f16x2(float lo, float hi) {
    __half2 h = __floats2half2_rn(lo, hi);
    return *(uint32_t*)&h;
}
// bf16x2 -> packed f32x2 (low elem in low word)
__device__ __forceinline__ unsigned long long bf2_f32x2(uint32_t u) {
    unsigned long long r;
    uint32_t lo = u << 16;
    uint32_t hi = u & 0xffff0000u;
    asm("mov.b64 %0, {%1, %2};" : "=l"(r) : "r"(lo), "r"(hi));
    return r;
}
#define FMA2(acc, a, b) \
    asm("fma.rn.f32x2 %0, %1, %2, %0;" : "+l"(acc) : "l"(a), "l"(b))

// ---------------- reset -------------------------------------------------------
__global__ void reset_kernel() {
    if (threadIdx.x == 0) { g_cnt[0] = 0; g_cnt[1] = 0; }
}

// ---------------- fused setup: prepack | wvec | compact -------------------------
__global__ void setup_kernel(const float* __restrict__ Wvc0, const float* __restrict__ Wvn0,
                             const float* __restrict__ a0,
                             const float* __restrict__ Wvc1, const float* __restrict__ Wvn1,
                             const float* __restrict__ a1,
                             const int* __restrict__ is_int) {
    const int bid = blockIdx.x;
    if (bid < 192) {
        // ---- prepack weights as packed fp16 pairs along k: g_Bh[k2][c] ----
        const int branch = bid >= 96;
        const float* Wvc = branch ? Wvc1 : Wvc0;
        const float* Wvn = branch ? Wvn1 : Wvn0;
        int i = (bid - branch * 96) * 256 + threadIdx.x;     // < 24576
        int k2 = i / NCOLS, c = i % NCOLS;
        const float* W;
        int h, o;
        if (c < ZC) { W = Wvc; h = c / FILT; o = c % FILT; }
        else        { W = Wvn; h = (c - ZC) / FILT; o = (c - ZC) % FILT; }
        float v0 = W[((size_t)h * VF + 2 * k2) * FILT + o];
        float v1 = W[((size_t)h * VF + 2 * k2 + 1) * FILT + o];
        g_Bh[branch][i] = pack_f16x2(v0, v1);
    } else if (bid < 288) {
        // ---- folded attention vectors ----
        int w = (bid - 192) * 8 + (threadIdx.x >> 5);        // < 768
        int lane = threadIdx.x & 31;
        const int branch = w >= NH * VF;
        int gw = w - branch * NH * VF;
        int h = gw / VF, k = gw % VF;
        const float* Wvc = branch ? Wvc1 : Wvc0;
        const float* Wvn = branch ? Wvn1 : Wvn0;
        const float* a   = branch ? a1 : a0;
        const float* wn = Wvn + ((size_t)h * VF + k) * FILT;
        const float* wc = Wvc + ((size_t)h * VF + k) * FILT;
        float v1 = wn[lane] * a[h * 128 + lane] + wn[lane + 32] * a[h * 128 + lane + 32];
        float v2 = wc[lane] * a[h * 128 + 64 + lane] + wc[lane + 32] * a[h * 128 + 96 + lane];
#pragma unroll
        for (int o = 16; o; o >>= 1) {
            v1 += __shfl_xor_sync(0xffffffffu, v1, o);
            v2 += __shfl_xor_sync(0xffffffffu, v2, o);
        }
        if (lane == 0) {
            g_w1[branch][h * VF + k] = v1;
            g_w2[branch][h * VF + k] = v2;
        }
    } else {
        // ---- compaction ----
        int n = (bid - 288) * 256 + threadIdx.x;
        if (n >= N_NODES) return;
        int b = (is_int[n] == 1) ? 0 : 1;
        int pos = atomicAdd(&g_cnt[b], 1);
        g_perm[b][pos] = n;
        g_meta[n].x = (pos << 1) | b;
    }
}

// ---------------- fp16 mma.sync GEMM (m16n8k16) + fused s1/s2 -------------------
#define AS2 68
#define BS2 136
#define A_U32 (128 * AS2)
#define B_BUF_U32 (64 * BS2)
#define GSMEM_BYTES ((A_U32 + 2 * B_BUF_U32) * 4)

__global__ void __launch_bounds__(256, 2)
gemm_kernel(const float* __restrict__ v_int, const float* __restrict__ v_nh) {
    extern __shared__ uint32_t sm[];
    uint32_t* As = sm;
    uint32_t* Bs0 = sm + A_U32;

    const int branch = blockIdx.y;
    const int cnt = g_cnt[branch];
    const int bm = blockIdx.x * 128;
    if (bm >= cnt) return;

    const int tid = threadIdx.x;
    const int lane = tid & 31;
    const int wid = tid >> 5;
    const int g = lane >> 2;
    const int tg = lane & 3;
    const int warp_m = wid & 3;
    const int warp_n = wid >> 2;

    const uint32_t sbB = smem_u32(Bs0);

    // ---- prefetch B slab 0 and 1 via cp.async ----
    {
        const int k2 = tid >> 2;
        const int coff = (tid & 3) * 32;
        const uint32_t* Bsrc = g_Bh[branch] + (size_t)k2 * NCOLS + coff;
        const uint32_t bdst = sbB + (uint32_t)(k2 * BS2 + coff) * 4u;
#pragma unroll
        for (int j = 0; j < 8; j++) cp_async16(bdst + j * 16, Bsrc + j * 4);
        CP_COMMIT();
#pragma unroll
        for (int j = 0; j < 8; j++)
            cp_async16(bdst + B_BUF_U32 * 4 + j * 16, Bsrc + 128 + j * 4);
        CP_COMMIT();
    }

    // ---- load + convert A tile to fp16 pairs ----
    const int r_row = tid >> 1;
    const int grl = bm + r_row;
    const int nd = g_perm[branch][grl < cnt ? grl : cnt - 1];
    {
        const int ch2 = (tid & 1) * 32;
        const float4* Ag = (const float4*)((branch ? v_nh : v_int) +
                                           (size_t)nd * VF + ch2 * 2);
        uint2* dst = (uint2*)(As + r_row * AS2 + ch2);
#pragma unroll
        for (int j = 0; j < 16; j++) {
            float4 v = Ag[j];
            dst[j] = make_uint2(pack_f16x2(v.x, v.y), pack_f16x2(v.z, v.w));
        }
    }

#pragma unroll 1
    for (int s = 0; s < 3; s++) {
        if (s < 2) { CP_WAIT(1); } else { CP_WAIT(0); }
        __syncthreads();

        const uint32_t* Bs = Bs0 + (s & 1) * B_BUF_U32;

        float acc[2][8][4];
#pragma unroll
        for (int mt = 0; mt < 2; mt++)
#pragma unroll
            for (int nt = 0; nt < 8; nt++)
#pragma unroll
                for (int q = 0; q < 4; q++) acc[mt][nt][q] = 0.f;

        const int ar = warp_m * 32 + g;
        const int cb = warp_n * 64 + g;
#pragma unroll
        for (int k2_0 = 0; k2_0 < 64; k2_0 += 8) {
            uint32_t a[2][4];
#pragma unroll
            for (int mt = 0; mt < 2; mt++) {
                const uint32_t* ap = As + (ar + mt * 16) * AS2 + k2_0 + tg;
                a[mt][0] = ap[0];
                a[mt][1] = ap[8 * AS2];
                a[mt][2] = ap[4];
                a[mt][3] = ap[8 * AS2 + 4];
            }
            uint32_t b[8][2];
            const uint32_t* bp0 = Bs + (k2_0 + tg) * BS2 + cb;
            const uint32_t* bp1 = bp0 + 4 * BS2;
#pragma unroll
            for (int nt = 0; nt < 8; nt++) {
                b[nt][0] = bp0[nt * 8];
                b[nt][1] = bp1[nt * 8];
            }
#pragma unroll
            for (int mt = 0; mt < 2; mt++)
#pragma unroll
                for (int nt = 0; nt < 8; nt++)
                    mma_f16(acc[mt][nt], a[mt], b[nt]);
        }

        __syncthreads();

        if (s == 0) {
            const int k2 = tid >> 2;
            const int coff = (tid & 3) * 32;
            const uint32_t* Bsrc = g_Bh[branch] + (size_t)k2 * NCOLS + 256 + coff;
            const uint32_t bdst = sbB + (uint32_t)(k2 * BS2 + coff) * 4u;
#pragma unroll
            for (int j = 0; j < 8; j++) cp_async16(bdst + j * 16, Bsrc + j * 4);
            CP_COMMIT();
        }

        // ---- epilogue ----
        const int cbase = s * 128 + warp_n * 64;
        if (cbase < ZC) {
            float* zb = g_Zc[branch];
            const int coff = cbase;
#pragma unroll
            for (int mt = 0; mt < 2; mt++) {
                const int r0 = warp_m * 32 + mt * 16 + g;
                const int gr0 = bm + r0, gr1 = gr0 + 8;
                float* row0 = zb + (size_t)gr0 * ZC + coff + 2 * tg;
                float* row1 = zb + (size_t)gr1 * ZC + coff + 2 * tg;
                const bool ok0 = gr0 < cnt, ok1 = gr1 < cnt;
#pragma unroll
                for (int nt = 0; nt < 8; nt++) {
                    if (ok0) *(float2*)(row0 + nt * 8) =
                        make_float2(acc[mt][nt][0], acc[mt][nt][1]);
                    if (ok1) *(float2*)(row1 + nt * 8) =
                        make_float2(acc[mt][nt][2], acc[mt][nt][3]);
                }
            }
        } else {
            __nv_bfloat16* zb = g_Znh[branch];
            const int coff = cbase - ZC;
#pragma unroll
            for (int mt = 0; mt < 2; mt++) {
                const int r0 = warp_m * 32 + mt * 16 + g;
                const int gr0 = bm + r0, gr1 = gr0 + 8;
                uint32_t* row0 = (uint32_t*)(zb + (size_t)gr0 * ZC + coff + 2 * tg);
                uint32_t* row1 = (uint32_t*)(zb + (size_t)gr1 * ZC + coff + 2 * tg);
                const bool ok0 = gr0 < cnt, ok1 = gr1 < cnt;
#pragma unroll
                for (int nt = 0; nt < 8; nt++) {
                    if (ok0) row0[nt * 4] = pack_bf16x2(acc[mt][nt][0], acc[mt][nt][1]);
                    if (ok1) row1[nt * 4] = pack_bf16x2(acc[mt][nt][2], acc[mt][nt][3]);
                }
            }
        }
    }

    // ---- fused s1/s2 from fp16 A tile ----
    float* wsv = (float*)Bs0;
    for (int i = tid; i < 6 * 128; i += 256) {
        int d = i >> 7, k = i & 127;
        wsv[d * 132 + k] = (d < 3) ? g_w1[branch][d * 128 + k]
                                   : g_w2[branch][(d - 3) * 128 + k];
    }
    __syncthreads();
    {
        const int dset = (tid & 1) * 3;
        const __half2* arow = (const __half2*)(As + r_row * AS2);
        const float* w0 = wsv + (dset + 0) * 132;
        const float* w1 = wsv + (dset + 1) * 132;
        const float* w2 = wsv + (dset + 2) * 132;
        float s0 = 0.f, s1 = 0.f, s2 = 0.f;
#pragma unroll 8
        for (int k2 = 0; k2 < 64; k2++) {
            float2 av = __half22float2(arow[k2]);
            s0 += av.x * w0[2 * k2] + av.y * w0[2 * k2 + 1];
            s1 += av.x * w1[2 * k2] + av.y * w1[2 * k2 + 1];
            s2 += av.x * w2[2 * k2] + av.y * w2[2 * k2 + 1];
        }
        if (grl < cnt) {
            if (tid & 1) {
                g_s2v[nd] = make_float4(s0, s1, s2,
                                        __int_as_float((grl << 1) | branch));
            } else {
                float* mp = (float*)&g_meta[nd];
                mp[1] = s0; mp[2] = s1; mp[3] = s2;
            }
        }
    }
}

// ---------------- attention + aggregate + epilogue ---------------------------
// One warp per (node, branch). Active-neighbor compaction via ballot/popc;
// no softmax max-shift (e bounded); packed f32x2 accumulation in the gather.
__global__ __launch_bounds__(256)
void attn_kernel(const int* __restrict__ idx_int, const int* __restrict__ idx_nh,
                 const float* __restrict__ e_int, const float* __restrict__ e_nh,
                 const float* __restrict__ bv_int, const float* __restrict__ bv_nh,
                 float* __restrict__ out) {
    const int branch = blockIdx.y;
    const int* __restrict__ idx   = branch ? idx_nh : idx_int;
    const float* __restrict__ edg = branch ? e_nh : e_int;
    const float* __restrict__ bv  = branch ? bv_nh : bv_int;
    float* __restrict__ o = out + (size_t)branch * N_NODES * OUTC;

    __shared__ int   soff[8][16];        // compacted byte offsets of active nbrs
    __shared__ float swt[8][NH][16];     // compacted weights

    const int wslot = threadIdx.x >> 5;
    const int lane = threadIdx.x & 31;
    const int n = (blockIdx.x * blockDim.x + threadIdx.x) >> 5;
    if (n >= N_NODES) return;

    // self metadata from g_s2v (s2 values + packed pos|branch)
    float4 sv = g_s2v[n];
    const int pb_self = __float_as_int(sv.w);
    const bool nact = (pb_self & 1) == branch;
    const int pos_self = pb_self >> 1;
    float s2h[NH];
    s2h[0] = nact ? sv.x : 0.f;
    s2h[1] = nact ? sv.y : 0.f;
    s2h[2] = nact ? sv.z : 0.f;
    // all lanes need s2h; lane-uniform load above is per-lane identical (same n)

    int myidx = -1;
    float myedge = 0.f;
    if (lane < KNBR) {
        myidx = idx[(size_t)n * KNBR + lane];
        myedge = edg[(size_t)n * KNBR + lane];
    }
    const bool has = (lane < KNBR) && (myidx >= 0);

    // neighbor metadata (one uint4: activity+pos + 3 s1 values)
    int hasg = 0, posk = 0;
    float s1k[NH] = {0.f, 0.f, 0.f};
    if (has) {
        int4 m = g_meta[myidx];
        hasg = ((m.x & 1) == branch) ? 1 : 0;
        posk = m.x >> 1;
        if (hasg) {
            s1k[0] = __int_as_float(m.y);
            s1k[1] = __int_as_float(m.z);
            s1k[2] = __int_as_float(m.w);
        }
    }

    // counts + compaction ranks via ballot
    const uint32_t bal_has = __ballot_sync(0xffffffffu, has);
    const uint32_t bal_g   = __ballot_sync(0xffffffffu, hasg != 0);
    const float invnorm = 1.f / fmaxf((float)__popc(bal_has), 1.f);
    const int cntg = __popc(bal_g);
    const int rank = __popc(bal_g & ((1u << lane) - 1u));
    if (hasg) soff[wslot][rank] = posk * (ZC * 2);

    // softmax per head (no max shift: e bounded, exp safe in fp32)
#pragma unroll
    for (int h = 0; h < NH; h++) {
        float e = has ? (s1k[h] + s2h[h]) * myedge : 0.f;
        float p = (lane < KNBR) ? __expf(e) : 0.f;
        float psum = p;
#pragma unroll
        for (int oo = 8; oo; oo >>= 1)
            psum += __shfl_xor_sync(0xffffffffu, psum, oo, 16);
        float rs = __fdividef(invnorm, psum);
        if (hasg) swt[wslot][h][rank] = p * rs;
    }
    __syncwarp();

    // ---- gather: lanes 0..23 own 8 contiguous bf16 channels ----
    const int myh = (lane < 24) ? (lane >> 3) : 0;
    const bool gl = lane < 24;
    unsigned long long a01 = 0, a23 = 0, a45 = 0, a67 = 0;

    const char* __restrict__ Zb = (const char*)g_Znh[branch];
    const int lane16 = lane * 16;
    for (int k = 0; k < cntg; k++) {
        if (gl) {
            int off = soff[wslot][k];
            float wk = swt[wslot][myh][k];
            unsigned long long wk2;
            asm("mov.b64 %0, {%1, %1};" : "=l"(wk2) : "f"(wk));
            uint4 v = *(const uint4*)(Zb + off + lane16);
            FMA2(a01, wk2, bf2_f32x2(v.x));
            FMA2(a23, wk2, bf2_f32x2(v.y));
            FMA2(a45, wk2, bf2_f32x2(v.z));
            FMA2(a67, wk2, bf2_f32x2(v.w));
        }
    }

    if (gl) {
        float2 f01 = *(float2*)&a01;
        float2 f23 = *(float2*)&a23;
        float2 f45 = *(float2*)&a45;
        float2 f67 = *(float2*)&a67;
        float4 zc0 = make_float4(0.f, 0.f, 0.f, 0.f), zc1 = zc0;
        if (nact) {
            const float4* zrow = (const float4*)(g_Zc[branch] +
                                                 (size_t)pos_self * ZC + lane * 8);
            zc0 = zrow[0];
            zc1 = zrow[1];
        }
        const float4* bvp = (const float4*)(bv + lane * 8);
        float4 b0 = bvp[0], b1 = bvp[1];
        float4 o0, o1;
        o0.x = fmaxf(f01.x + zc0.x + b0.x, 0.f);
        o0.y = fmaxf(f01.y + zc0.y + b0.y, 0.f);
        o0.z = fmaxf(f23.x + zc0.z + b0.z, 0.f);
        o0.w = fmaxf(f23.y + zc0.w + b0.w, 0.f);
        o1.x = fmaxf(f45.x + zc1.x + b1.x, 0.f);
        o1.y = fmaxf(f45.y + zc1.y + b1.y, 0.f);
        o1.z = fmaxf(f67.x + zc1.z + b1.z, 0.f);
        o1.w = fmaxf(f67.y + zc1.w + b1.w, 0.f);
        float4* op = (float4*)(o + (size_t)n * OUTC + lane * 8);
        op[0] = o0;
        op[1] = o1;
    }
}

// ---------------- launch ---------------------------------------------------------
extern "C" void kernel_launch(void* const* d_in, const int* in_sizes, int n_in,
                              void* d_out, int out_size) {
    const float* vertices_int = (const float*)d_in[0];
    const float* vertices_nh  = (const float*)d_in[1];
    const int*   nh_indices   = (const int*)d_in[2];
    const int*   int_indices  = (const int*)d_in[3];
    const float* nh_edges     = (const float*)d_in[4];
    const float* int_edges    = (const float*)d_in[5];
    const int*   is_int       = (const int*)d_in[6];
    const float* Wvc_int      = (const float*)d_in[7];
    const float* Wvc_nh       = (const float*)d_in[8];
    const float* Wvn_int      = (const float*)d_in[9];
    const float* Wvn_nh       = (const float*)d_in[10];
    const float* bv_int       = (const float*)d_in[11];
    const float* bv_nh        = (const float*)d_in[12];
    const float* a_int        = (const float*)d_in[13];
    const float* a_nh         = (const float*)d_in[14];
    float* out = (float*)d_out;

    cudaFuncSetAttribute(gemm_kernel,
                         cudaFuncAttributeMaxDynamicSharedMemorySize, GSMEM_BYTES);

    reset_kernel<<<1, 32>>>();
    setup_kernel<<<288 + (N_NODES + 255) / 256, 256>>>(
        Wvc_int, Wvn_int, a_int, Wvc_nh, Wvn_nh, a_nh, is_int);

    dim3 gg((N_NODES + 127) / 128, 2);
    gemm_kernel<<<gg, 256, GSMEM_BYTES>>>(vertices_int, vertices_nh);

    dim3 ag((N_NODES + 7) / 8, 2);
    attn_kernel<<<ag, 256>>>(int_indices, nh_indices, int_edges, nh_edges,
                             bv_int, bv_nh, out);
}